// round 4
// baseline (speedup 1.0000x reference)
#include <cuda_runtime.h>
#include <cuda_bf16.h>

// Problem constants
#define BB 4
#define LL 512
#define DD 256
#define HH 8
#define DH 32
#define QK_SCALE 0.17677669529663687f  // 1/sqrt(32)

typedef unsigned long long ull;

// ---------------- f32x2 packed-pair helpers (Blackwell FFMA2) ----------------
__device__ __forceinline__ ull pack2(float x, float y) {
    ull d; asm("mov.b64 %0, {%1, %2};" : "=l"(d) : "f"(x), "f"(y)); return d;
}
__device__ __forceinline__ float2 unpack2(ull v) {
    float2 r; asm("mov.b64 {%0, %1}, %2;" : "=f"(r.x), "=f"(r.y) : "l"(v)); return r;
}
__device__ __forceinline__ ull fma2(ull a, ull b, ull c) {
    ull d; asm("fma.rn.f32x2 %0, %1, %2, %3;" : "=l"(d) : "l"(a), "l"(b), "l"(c)); return d;
}

// ---------------- device scratch ----------------
__device__ float g_q[BB * HH * LL * DH];   // scaled q, (B,H,L,DH)
__device__ float g_k[BB * HH * LL * DH];
__device__ float g_v[BB * HH * LL * DH];
__device__ float g_ctx[BB * LL * DD];      // ctx in (B,L,D) layout
__device__ unsigned char g_idx[BB * LL * LL]; // fused mask+distance bucket index
__device__ int   g_mask_kind;              // 0=int32, 1=float32, 2=bytes

// ---------------- mask dtype detector ----------------
__global__ void detect_mask_kernel(const unsigned int* mw) {
    __shared__ int flags[2];
    if (threadIdx.x < 2) flags[threadIdx.x] = 0;
    __syncthreads();
    int f1 = 0, f2 = 0;
    for (int i = threadIdx.x; i < 4096; i += blockDim.x) {
        unsigned int w = mw[i];
        if (w == 0u || w == 1u) continue;
        if (w == 0x3F800000u) { f1 = 1; continue; }
        f2 = 1;
    }
    if (f1) atomicOr(&flags[0], 1);
    if (f2) atomicOr(&flags[1], 1);
    __syncthreads();
    if (threadIdx.x == 0)
        g_mask_kind = flags[1] ? 2 : (flags[0] ? 1 : 0);
}

// ---------------- prep: idx = mask ? 12 : dist (bytes) ----------------
__global__ void prep_idx_kernel(const void* __restrict__ mask,
                                const int* __restrict__ dist) {
    const int kind = g_mask_kind;
    const int i = blockIdx.x * 256 + threadIdx.x;      // over 1M/4
    int4 d4 = ((const int4*)dist)[i];
    int m0, m1, m2, m3;
    if (kind == 2) {
        uchar4 m = ((const uchar4*)mask)[i];
        m0 = m.x; m1 = m.y; m2 = m.z; m3 = m.w;
    } else if (kind == 1) {
        float4 m = ((const float4*)mask)[i];
        m0 = (m.x != 0.0f); m1 = (m.y != 0.0f); m2 = (m.z != 0.0f); m3 = (m.w != 0.0f);
    } else {
        int4 m = ((const int4*)mask)[i];
        m0 = m.x; m1 = m.y; m2 = m.z; m3 = m.w;
    }
    uchar4 o;
    o.x = m0 ? 12 : (unsigned char)d4.x;
    o.y = m1 ? 12 : (unsigned char)d4.y;
    o.z = m2 ? 12 : (unsigned char)d4.z;
    o.w = m3 ? 12 : (unsigned char)d4.w;
    ((uchar4*)g_idx)[i] = o;
}

// ---------------- kernel 1: fused QKV projection GEMM (f32x2) ----------------
// C(2048x256) = X @ W + bias, permuted writes. 64x64 tile, pairs over M rows.
__global__ __launch_bounds__(256) void qkv_gemm_kernel(
        const float* __restrict__ X,
        const float* __restrict__ Wq, const float* __restrict__ bq,
        const float* __restrict__ Wk, const float* __restrict__ bk,
        const float* __restrict__ Wv, const float* __restrict__ bv) {
    const int z = blockIdx.z;
    const float* W    = (z == 0) ? Wq : (z == 1 ? Wk : Wv);
    const float* bias = (z == 0) ? bq : (z == 1 ? bk : bv);
    float* out        = (z == 0) ? g_q : (z == 1 ? g_k : g_v);
    const float scale = (z == 0) ? QK_SCALE : 1.0f;

    __shared__ float AsT[64 * 66];   // [k][m] transposed, pad 66
    __shared__ float Bs[64 * 68];    // [k][n]

    const int t = threadIdx.x;
    const int tr = (t >> 4) * 4;     // m base (pairs tr..tr+3)
    const int tc = (t & 15) * 4;     // n base
    const int rowBase = blockIdx.y * 64;
    const int colBase = blockIdx.x * 64;

    ull acc2[2][4];
#pragma unroll
    for (int p = 0; p < 2; p++)
#pragma unroll
        for (int j = 0; j < 4; j++) acc2[p][j] = 0ull;

    for (int k0 = 0; k0 < DD; k0 += 64) {
        for (int i = t; i < 1024; i += 256) {
            int m = i >> 4, k4 = (i & 15) * 4;
            float4 x = *(const float4*)(X + (rowBase + m) * DD + k0 + k4);
            AsT[(k4 + 0) * 66 + m] = x.x;
            AsT[(k4 + 1) * 66 + m] = x.y;
            AsT[(k4 + 2) * 66 + m] = x.z;
            AsT[(k4 + 3) * 66 + m] = x.w;
        }
        for (int i = t; i < 1024; i += 256) {
            int k = i >> 4, n4 = (i & 15) * 4;
            *(float4*)(Bs + k * 68 + n4) = *(const float4*)(W + (k0 + k) * DD + colBase + n4);
        }
        __syncthreads();
#pragma unroll 16
        for (int kk = 0; kk < 64; kk++) {
            ull a0 = *(const ull*)(AsT + kk * 66 + tr);
            ull a1 = *(const ull*)(AsT + kk * 66 + tr + 2);
            float4 b4 = *(const float4*)(Bs + kk * 68 + tc);
            ull b0 = pack2(b4.x, b4.x);
            ull b1 = pack2(b4.y, b4.y);
            ull b2 = pack2(b4.z, b4.z);
            ull b3 = pack2(b4.w, b4.w);
            acc2[0][0] = fma2(a0, b0, acc2[0][0]);
            acc2[0][1] = fma2(a0, b1, acc2[0][1]);
            acc2[0][2] = fma2(a0, b2, acc2[0][2]);
            acc2[0][3] = fma2(a0, b3, acc2[0][3]);
            acc2[1][0] = fma2(a1, b0, acc2[1][0]);
            acc2[1][1] = fma2(a1, b1, acc2[1][1]);
            acc2[1][2] = fma2(a1, b2, acc2[1][2]);
            acc2[1][3] = fma2(a1, b3, acc2[1][3]);
        }
        __syncthreads();
    }

    const int col0 = colBase + tc;
    const int h = col0 >> 5, d = col0 & 31;
    const float4 bi = *(const float4*)(bias + col0);
#pragma unroll
    for (int p = 0; p < 2; p++) {
        float2 c0 = unpack2(acc2[p][0]);
        float2 c1 = unpack2(acc2[p][1]);
        float2 c2 = unpack2(acc2[p][2]);
        float2 c3 = unpack2(acc2[p][3]);
#pragma unroll
        for (int s = 0; s < 2; s++) {
            int row = rowBase + tr + p * 2 + s;
            int b = row >> 9, l = row & 511;
            float4 o;
            o.x = ((s ? c0.y : c0.x) + bi.x) * scale;
            o.y = ((s ? c1.y : c1.x) + bi.y) * scale;
            o.z = ((s ? c2.y : c2.x) + bi.z) * scale;
            o.w = ((s ? c3.y : c3.x) + bi.w) * scale;
            *(float4*)(out + (((b * HH + h) * LL) + l) * DH + d) = o;
        }
    }
}

// ---------------- kernel 2: fully fused attention ----------------
// per block: one bh, 32 q rows. P precompute + scores + softmax + attn write + ctx.
__global__ __launch_bounds__(256, 2) void attn_kernel(
        const float* __restrict__ uvec,
        const float* __restrict__ vvec,
        const float* __restrict__ rel_table,
        float* __restrict__ attn) {
    extern __shared__ float sm[];
    float* S    = sm;                  // [32][516] scores/exp
    float* KV   = S + 32 * 516;        // 8320 floats: KsT[32][260] or Vs[128][36] or tbl
    float* qu   = KV + 8320;           // [32][33]
    float* Ps   = qu + 32 * 33;        // [32][16]
    float* invp = Ps + 32 * 16;        // [32]

    const int bh = blockIdx.y;
    const int b = bh >> 3, h = bh & 7;
    const int q0 = blockIdx.x * 32;
    const int t = threadIdx.x;

    // -------- phase 0: qu = q+v, table slice, P --------
    {
        int q = t >> 3, d4 = (t & 7) * 4;
        float4 qv = *(const float4*)(g_q + ((size_t)bh * LL + q0 + q) * DH + d4);
        float4 vv = *(const float4*)(vvec + h * DH + d4);
        qu[q * 33 + d4 + 0] = qv.x + vv.x;
        qu[q * 33 + d4 + 1] = qv.y + vv.y;
        qu[q * 33 + d4 + 2] = qv.z + vv.z;
        qu[q * 33 + d4 + 3] = qv.w + vv.w;
    }
    float* tbl = KV;   // [12][33]
    for (int i = t; i < 384; i += 256) {
        int bu = i >> 5, d = i & 31;
        tbl[bu * 33 + d] = rel_table[bu * DD + h * DH + d];
    }
    __syncthreads();
    for (int j = t; j < 384; j += 256) {
        int q = j / 12, bu = j - q * 12;
        const float* qp = qu + q * 33;
        const float* tp = tbl + bu * 33;
        float s = 0.0f;
#pragma unroll
        for (int d = 0; d < 32; d++) s = fmaf(qp[d], tp[d], s);
        Ps[q * 16 + bu] = s;
    }
    if (t < 32) Ps[t * 16 + 12] = -1e18f;
    __syncthreads();
    // qu: (q+v) -> (q+u)
    {
        int q = t >> 3, d4 = (t & 7) * 4;
        float4 uu = *(const float4*)(uvec + h * DH + d4);
        float4 vv = *(const float4*)(vvec + h * DH + d4);
        qu[q * 33 + d4 + 0] += uu.x - vv.x;
        qu[q * 33 + d4 + 1] += uu.y - vv.y;
        qu[q * 33 + d4 + 2] += uu.z - vv.z;
        qu[q * 33 + d4 + 3] += uu.w - vv.w;
    }

    // -------- phase 1: scores (f32x2, pairs over k) --------
    const int tq = (t >> 5) * 4;       // warp-uniform q base
    const int tc2 = t & 31;            // k-pair lane

    for (int kc = 0; kc < LL; kc += 256) {
        __syncthreads();
        // load K chunk transposed: KsT[d][k], stride 260
        for (int i = t; i < 2048; i += 256) {
            int k = i >> 3, d4 = (i & 7) * 4;
            float4 kv = *(const float4*)(g_k + ((size_t)bh * LL + kc + k) * DH + d4);
            KV[(d4 + 0) * 260 + k] = kv.x;
            KV[(d4 + 1) * 260 + k] = kv.y;
            KV[(d4 + 2) * 260 + k] = kv.z;
            KV[(d4 + 3) * 260 + k] = kv.w;
        }
        __syncthreads();

        ull acc2[4][4];
#pragma unroll
        for (int i = 0; i < 4; i++)
#pragma unroll
            for (int j = 0; j < 4; j++) acc2[i][j] = 0ull;

#pragma unroll
        for (int d = 0; d < DH; d++) {
            ull a2[4];
#pragma unroll
            for (int i = 0; i < 4; i++) {
                float a = qu[(tq + i) * 33 + d];
                a2[i] = pack2(a, a);
            }
            const float* Kd = KV + d * 260 + 2 * tc2;
#pragma unroll
            for (int j = 0; j < 4; j++) {
                ull b2 = *(const ull*)(Kd + 64 * j);
                acc2[0][j] = fma2(a2[0], b2, acc2[0][j]);
                acc2[1][j] = fma2(a2[1], b2, acc2[1][j]);
                acc2[2][j] = fma2(a2[2], b2, acc2[2][j]);
                acc2[3][j] = fma2(a2[3], b2, acc2[3][j]);
            }
        }

        // epilogue: add P[idx], store raw scores into S
#pragma unroll
        for (int i = 0; i < 4; i++) {
            int q = tq + i;
            const unsigned char* ip = g_idx + ((size_t)(b * LL + q0 + q)) * LL + kc + 2 * tc2;
            const float* Pq = Ps + q * 16;
            float* Sr = S + q * 516 + kc + 2 * tc2;
#pragma unroll
            for (int j = 0; j < 4; j++) {
                unsigned int u2 = *(const unsigned short*)(ip + 64 * j);
                float2 s2 = unpack2(acc2[i][j]);
                float2 o;
                o.x = s2.x + Pq[u2 & 255];
                o.y = s2.y + Pq[(u2 >> 8) & 255];
                *(float2*)(Sr + 64 * j) = o;
            }
        }
    }
    __syncthreads();

    // -------- phase 2: softmax rows, write normalized attn --------
    {
        const int w = t >> 5, lane = t & 31;
#pragma unroll
        for (int rr = 0; rr < 4; rr++) {
            int r = w * 4 + rr;
            float* Sr = S + r * 516;
            float m = -3.4e38f;
            for (int c = lane; c < LL; c += 32) m = fmaxf(m, Sr[c]);
#pragma unroll
            for (int o = 16; o; o >>= 1) m = fmaxf(m, __shfl_xor_sync(0xffffffffu, m, o));
            float s = 0.0f;
            for (int c = lane; c < LL; c += 32) {
                float e = __expf(Sr[c] - m);
                Sr[c] = e;
                s += e;
            }
#pragma unroll
            for (int o = 16; o; o >>= 1) s += __shfl_xor_sync(0xffffffffu, s, o);
            if (lane == 0) invp[r] = 1.0f / s;
        }
    }
    __syncthreads();

    float* arow = attn + ((size_t)(bh * LL + q0)) * LL;
    for (int i = t; i < 32 * 128; i += 256) {
        int r = i >> 7, c4 = (i & 127) << 2;
        float iv = invp[r];
        float4 e = *(const float4*)(S + r * 516 + c4);
        float4 o = make_float4(e.x * iv, e.y * iv, e.z * iv, e.w * iv);
        *(float4*)(arow + r * LL + c4) = o;
    }

    // -------- phase 3: ctx = S @ V (f32x2, pairs over d) --------
    const int qq = t >> 3;
    const int d4 = (t & 7) * 4;
    ull acc0 = 0ull, acc1 = 0ull;

    for (int kc = 0; kc < LL; kc += 128) {
        __syncthreads();
        for (int i = t; i < 1024; i += 256) {
            int k = i >> 3, dd = (i & 7) * 4;
            *(float4*)(KV + k * 36 + dd) =
                *(const float4*)(g_v + ((size_t)bh * LL + kc + k) * DH + dd);
        }
        __syncthreads();
        const float* Sq = S + qq * 516 + kc;
#pragma unroll 8
        for (int kk = 0; kk < 128; kk++) {
            float a = Sq[kk];
            ull a2 = pack2(a, a);
            const float* Vr = KV + kk * 36 + d4;
            acc0 = fma2(a2, *(const ull*)(Vr), acc0);
            acc1 = fma2(a2, *(const ull*)(Vr + 2), acc1);
        }
    }
    const float iv = invp[qq];
    float2 c0 = unpack2(acc0), c1 = unpack2(acc1);
    float4 o = make_float4(c0.x * iv, c0.y * iv, c1.x * iv, c1.y * iv);
    *(float4*)(g_ctx + ((size_t)(b * LL) + q0 + qq) * DD + h * DH + d4) = o;
}

// ---------------- kernel 3: output GEMM ctx @ Wo + bo (f32x2) ----------------
__global__ __launch_bounds__(256) void out_gemm_kernel(
        const float* __restrict__ Wo,
        const float* __restrict__ bo,
        float* __restrict__ out) {
    __shared__ float AsT[64 * 66];
    __shared__ float Bs[64 * 68];

    const int t = threadIdx.x;
    const int tr = (t >> 4) * 4;
    const int tc = (t & 15) * 4;
    const int rowBase = blockIdx.y * 64;
    const int colBase = blockIdx.x * 64;

    ull acc2[2][4];
#pragma unroll
    for (int p = 0; p < 2; p++)
#pragma unroll
        for (int j = 0; j < 4; j++) acc2[p][j] = 0ull;

    for (int k0 = 0; k0 < DD; k0 += 64) {
        for (int i = t; i < 1024; i += 256) {
            int m = i >> 4, k4 = (i & 15) * 4;
            float4 x = *(const float4*)(g_ctx + (rowBase + m) * DD + k0 + k4);
            AsT[(k4 + 0) * 66 + m] = x.x;
            AsT[(k4 + 1) * 66 + m] = x.y;
            AsT[(k4 + 2) * 66 + m] = x.z;
            AsT[(k4 + 3) * 66 + m] = x.w;
        }
        for (int i = t; i < 1024; i += 256) {
            int k = i >> 4, n4 = (i & 15) * 4;
            *(float4*)(Bs + k * 68 + n4) = *(const float4*)(Wo + (k0 + k) * DD + colBase + n4);
        }
        __syncthreads();
#pragma unroll 16
        for (int kk = 0; kk < 64; kk++) {
            ull a0 = *(const ull*)(AsT + kk * 66 + tr);
            ull a1 = *(const ull*)(AsT + kk * 66 + tr + 2);
            float4 b4 = *(const float4*)(Bs + kk * 68 + tc);
            ull b0 = pack2(b4.x, b4.x);
            ull b1 = pack2(b4.y, b4.y);
            ull b2 = pack2(b4.z, b4.z);
            ull b3 = pack2(b4.w, b4.w);
            acc2[0][0] = fma2(a0, b0, acc2[0][0]);
            acc2[0][1] = fma2(a0, b1, acc2[0][1]);
            acc2[0][2] = fma2(a0, b2, acc2[0][2]);
            acc2[0][3] = fma2(a0, b3, acc2[0][3]);
            acc2[1][0] = fma2(a1, b0, acc2[1][0]);
            acc2[1][1] = fma2(a1, b1, acc2[1][1]);
            acc2[1][2] = fma2(a1, b2, acc2[1][2]);
            acc2[1][3] = fma2(a1, b3, acc2[1][3]);
        }
        __syncthreads();
    }

    const int col0 = colBase + tc;
    const float4 bi = *(const float4*)(bo + col0);
#pragma unroll
    for (int p = 0; p < 2; p++) {
        float2 c0 = unpack2(acc2[p][0]);
        float2 c1 = unpack2(acc2[p][1]);
        float2 c2 = unpack2(acc2[p][2]);
        float2 c3 = unpack2(acc2[p][3]);
#pragma unroll
        for (int s = 0; s < 2; s++) {
            int row = rowBase + tr + p * 2 + s;
            float4 o;
            o.x = (s ? c0.y : c0.x) + bi.x;
            o.y = (s ? c1.y : c1.x) + bi.y;
            o.z = (s ? c2.y : c2.x) + bi.z;
            o.w = (s ? c3.y : c3.x) + bi.w;
            *(float4*)(out + row * DD + col0) = o;
        }
    }
}

// ---------------- launch ----------------
extern "C" void kernel_launch(void* const* d_in, const int* in_sizes, int n_in,
                              void* d_out, int out_size) {
    const float* X         = (const float*)d_in[0];
    const void*  mask      = d_in[1];
    const int*   distances = (const int*)d_in[2];
    const float* Wq        = (const float*)d_in[3];
    const float* bq        = (const float*)d_in[4];
    const float* Wk        = (const float*)d_in[5];
    const float* bk        = (const float*)d_in[6];
    const float* Wv        = (const float*)d_in[7];
    const float* bv        = (const float*)d_in[8];
    const float* Wo        = (const float*)d_in[9];
    const float* bo        = (const float*)d_in[10];
    const float* rel_table = (const float*)d_in[11];
    const float* uvec      = (const float*)d_in[12];
    const float* vvec      = (const float*)d_in[13];

    float* out  = (float*)d_out;                       // (B,L,D)
    float* attn = (float*)d_out + BB * LL * DD;        // (B,H,L,L)

    const int attn_smem = (32 * 516 + 8320 + 32 * 33 + 32 * 16 + 32) * 4;
    static int smem_set = 0;
    if (!smem_set) {
        cudaFuncSetAttribute(attn_kernel,
                             cudaFuncAttributeMaxDynamicSharedMemorySize,
                             attn_smem);
        smem_set = 1;
    }

    detect_mask_kernel<<<1, 256>>>((const unsigned int*)mask);
    prep_idx_kernel<<<1024, 256>>>(mask, distances);
    qkv_gemm_kernel<<<dim3(4, 32, 3), 256>>>(X, Wq, bq, Wk, bk, Wv, bv);
    attn_kernel<<<dim3(16, 32), 256, attn_smem>>>(uvec, vvec, rel_table, attn);
    out_gemm_kernel<<<dim3(4, 32), 256>>>(Wo, bo, out);
}

// round 5
// speedup vs baseline: 1.1322x; 1.1322x over previous
#include <cuda_runtime.h>
#include <cuda_bf16.h>

// Problem constants
#define BB 4
#define LL 512
#define DD 256
#define HH 8
#define DH 32
#define QK_SCALE 0.17677669529663687f  // 1/sqrt(32)

typedef unsigned long long ull;

// ---------------- f32x2 packed-pair helpers (Blackwell FFMA2) ----------------
__device__ __forceinline__ ull pack2(float x, float y) {
    ull d; asm("mov.b64 %0, {%1, %2};" : "=l"(d) : "f"(x), "f"(y)); return d;
}
__device__ __forceinline__ float2 unpack2(ull v) {
    float2 r; asm("mov.b64 {%0, %1}, %2;" : "=f"(r.x), "=f"(r.y) : "l"(v)); return r;
}
__device__ __forceinline__ ull fma2(ull a, ull b, ull c) {
    ull d; asm("fma.rn.f32x2 %0, %1, %2, %3;" : "=l"(d) : "l"(a), "l"(b), "l"(c)); return d;
}

// ---------------- device scratch ----------------
__device__ float g_q[BB * HH * LL * DH];   // scaled q, (B,H,L,DH)
__device__ float g_k[BB * HH * LL * DH];
__device__ float g_v[BB * HH * LL * DH];
__device__ float g_ctx[BB * LL * DD];      // ctx in (B,L,D) layout
__device__ unsigned char g_idx[BB * LL * LL]; // fused mask+distance bucket index
__device__ int   g_mask_kind;              // 0=int32, 1=float32, 2=bytes

// ---------------- mask dtype detector ----------------
__global__ void detect_mask_kernel(const unsigned int* mw) {
    __shared__ int flags[2];
    if (threadIdx.x < 2) flags[threadIdx.x] = 0;
    __syncthreads();
    int f1 = 0, f2 = 0;
    for (int i = threadIdx.x; i < 4096; i += blockDim.x) {
        unsigned int w = mw[i];
        if (w == 0u || w == 1u) continue;
        if (w == 0x3F800000u) { f1 = 1; continue; }
        f2 = 1;
    }
    if (f1) atomicOr(&flags[0], 1);
    if (f2) atomicOr(&flags[1], 1);
    __syncthreads();
    if (threadIdx.x == 0)
        g_mask_kind = flags[1] ? 2 : (flags[0] ? 1 : 0);
}

// ---------------- prep: idx = mask ? 12 : dist (bytes) ----------------
__global__ void prep_idx_kernel(const void* __restrict__ mask,
                                const int* __restrict__ dist) {
    const int kind = g_mask_kind;
    const int i = blockIdx.x * 256 + threadIdx.x;      // over 1M/4
    int4 d4 = ((const int4*)dist)[i];
    int m0, m1, m2, m3;
    if (kind == 2) {
        uchar4 m = ((const uchar4*)mask)[i];
        m0 = m.x; m1 = m.y; m2 = m.z; m3 = m.w;
    } else if (kind == 1) {
        float4 m = ((const float4*)mask)[i];
        m0 = (m.x != 0.0f); m1 = (m.y != 0.0f); m2 = (m.z != 0.0f); m3 = (m.w != 0.0f);
    } else {
        int4 m = ((const int4*)mask)[i];
        m0 = m.x; m1 = m.y; m2 = m.z; m3 = m.w;
    }
    uchar4 o;
    o.x = m0 ? 12 : (unsigned char)d4.x;
    o.y = m1 ? 12 : (unsigned char)d4.y;
    o.z = m2 ? 12 : (unsigned char)d4.z;
    o.w = m3 ? 12 : (unsigned char)d4.w;
    ((uchar4*)g_idx)[i] = o;
}

// ---------------- kernel 1: fused QKV projection GEMM (f32x2) ----------------
__global__ __launch_bounds__(256) void qkv_gemm_kernel(
        const float* __restrict__ X,
        const float* __restrict__ Wq, const float* __restrict__ bq,
        const float* __restrict__ Wk, const float* __restrict__ bk,
        const float* __restrict__ Wv, const float* __restrict__ bv) {
    const int z = blockIdx.z;
    const float* W    = (z == 0) ? Wq : (z == 1 ? Wk : Wv);
    const float* bias = (z == 0) ? bq : (z == 1 ? bk : bv);
    float* out        = (z == 0) ? g_q : (z == 1 ? g_k : g_v);
    const float scale = (z == 0) ? QK_SCALE : 1.0f;

    __shared__ float AsT[64 * 66];   // [k][m] transposed
    __shared__ float Bs[64 * 68];    // [k][n]

    const int t = threadIdx.x;
    const int tr = (t >> 4) * 4;
    const int tc = (t & 15) * 4;
    const int rowBase = blockIdx.y * 64;
    const int colBase = blockIdx.x * 64;

    ull acc2[2][4];
#pragma unroll
    for (int p = 0; p < 2; p++)
#pragma unroll
        for (int j = 0; j < 4; j++) acc2[p][j] = 0ull;

    for (int k0 = 0; k0 < DD; k0 += 64) {
        for (int i = t; i < 1024; i += 256) {
            int m = i >> 4, k4 = (i & 15) * 4;
            float4 x = *(const float4*)(X + (rowBase + m) * DD + k0 + k4);
            AsT[(k4 + 0) * 66 + m] = x.x;
            AsT[(k4 + 1) * 66 + m] = x.y;
            AsT[(k4 + 2) * 66 + m] = x.z;
            AsT[(k4 + 3) * 66 + m] = x.w;
        }
        for (int i = t; i < 1024; i += 256) {
            int k = i >> 4, n4 = (i & 15) * 4;
            *(float4*)(Bs + k * 68 + n4) = *(const float4*)(W + (k0 + k) * DD + colBase + n4);
        }
        __syncthreads();
#pragma unroll 16
        for (int kk = 0; kk < 64; kk++) {
            ull a0 = *(const ull*)(AsT + kk * 66 + tr);
            ull a1 = *(const ull*)(AsT + kk * 66 + tr + 2);
            float4 b4 = *(const float4*)(Bs + kk * 68 + tc);
            ull b0 = pack2(b4.x, b4.x);
            ull b1 = pack2(b4.y, b4.y);
            ull b2 = pack2(b4.z, b4.z);
            ull b3 = pack2(b4.w, b4.w);
            acc2[0][0] = fma2(a0, b0, acc2[0][0]);
            acc2[0][1] = fma2(a0, b1, acc2[0][1]);
            acc2[0][2] = fma2(a0, b2, acc2[0][2]);
            acc2[0][3] = fma2(a0, b3, acc2[0][3]);
            acc2[1][0] = fma2(a1, b0, acc2[1][0]);
            acc2[1][1] = fma2(a1, b1, acc2[1][1]);
            acc2[1][2] = fma2(a1, b2, acc2[1][2]);
            acc2[1][3] = fma2(a1, b3, acc2[1][3]);
        }
        __syncthreads();
    }

    const int col0 = colBase + tc;
    const int h = col0 >> 5, d = col0 & 31;
    const float4 bi = *(const float4*)(bias + col0);
#pragma unroll
    for (int p = 0; p < 2; p++) {
        float2 c0 = unpack2(acc2[p][0]);
        float2 c1 = unpack2(acc2[p][1]);
        float2 c2 = unpack2(acc2[p][2]);
        float2 c3 = unpack2(acc2[p][3]);
#pragma unroll
        for (int s = 0; s < 2; s++) {
            int row = rowBase + tr + p * 2 + s;
            int b = row >> 9, l = row & 511;
            float4 o;
            o.x = ((s ? c0.y : c0.x) + bi.x) * scale;
            o.y = ((s ? c1.y : c1.x) + bi.y) * scale;
            o.z = ((s ? c2.y : c2.x) + bi.z) * scale;
            o.w = ((s ? c3.y : c3.x) + bi.w) * scale;
            *(float4*)(out + (((b * HH + h) * LL) + l) * DH + d) = o;
        }
    }
}

// ---------------- kernel 2: fully fused attention ----------------
// smem layout (floats): S 16512 | KV 8848 | qu 1056 | Ps 512 | invp 32
//   KV union: scores KsT[32][260]=8320 ; ctx Vs[128][36]=4608 + red 4240 ; tbl 396
#define KV_FLOATS 8848
__global__ __launch_bounds__(256, 2) void attn_kernel(
        const float* __restrict__ uvec,
        const float* __restrict__ vvec,
        const float* __restrict__ rel_table,
        float* __restrict__ attn) {
    extern __shared__ float sm[];
    float* S    = sm;                  // [32][516] scores/exp
    float* KV   = S + 32 * 516;
    float* qu   = KV + KV_FLOATS;      // [32][33]
    float* Ps   = qu + 32 * 33;        // [32][16]
    float* invp = Ps + 32 * 16;        // [32]

    const int bh = blockIdx.y;
    const int b = bh >> 3, h = bh & 7;
    const int q0 = blockIdx.x * 32;
    const int t = threadIdx.x;

    // -------- phase 0: qu = q+v, table slice, P --------
    {
        int q = t >> 3, d4 = (t & 7) * 4;
        float4 qv = *(const float4*)(g_q + ((size_t)bh * LL + q0 + q) * DH + d4);
        float4 vv = *(const float4*)(vvec + h * DH + d4);
        qu[q * 33 + d4 + 0] = qv.x + vv.x;
        qu[q * 33 + d4 + 1] = qv.y + vv.y;
        qu[q * 33 + d4 + 2] = qv.z + vv.z;
        qu[q * 33 + d4 + 3] = qv.w + vv.w;
    }
    float* tbl = KV;   // [12][33]
    for (int i = t; i < 384; i += 256) {
        int bu = i >> 5, d = i & 31;
        tbl[bu * 33 + d] = rel_table[bu * DD + h * DH + d];
    }
    __syncthreads();
    for (int j = t; j < 384; j += 256) {
        int q = j / 12, bu = j - q * 12;
        const float* qp = qu + q * 33;
        const float* tp = tbl + bu * 33;
        float s = 0.0f;
#pragma unroll
        for (int d = 0; d < 32; d++) s = fmaf(qp[d], tp[d], s);
        Ps[q * 16 + bu] = s;
    }
    if (t < 32) Ps[t * 16 + 12] = -1e18f;
    __syncthreads();
    // qu: (q+v) -> (q+u)
    {
        int q = t >> 3, d4 = (t & 7) * 4;
        float4 uu = *(const float4*)(uvec + h * DH + d4);
        float4 vv = *(const float4*)(vvec + h * DH + d4);
        qu[q * 33 + d4 + 0] += uu.x - vv.x;
        qu[q * 33 + d4 + 1] += uu.y - vv.y;
        qu[q * 33 + d4 + 2] += uu.z - vv.z;
        qu[q * 33 + d4 + 3] += uu.w - vv.w;
    }

    // -------- phase 1: scores (f32x2, pairs over k) --------
    const int tq = (t >> 5) * 4;       // warp-uniform q base
    const int tc2 = t & 31;            // k-pair lane

    for (int kc = 0; kc < LL; kc += 256) {
        __syncthreads();
        // load K chunk transposed: KsT[d][k], stride 260
        for (int i = t; i < 2048; i += 256) {
            int k = i >> 3, d4 = (i & 7) * 4;
            float4 kv = *(const float4*)(g_k + ((size_t)bh * LL + kc + k) * DH + d4);
            KV[(d4 + 0) * 260 + k] = kv.x;
            KV[(d4 + 1) * 260 + k] = kv.y;
            KV[(d4 + 2) * 260 + k] = kv.z;
            KV[(d4 + 3) * 260 + k] = kv.w;
        }
        __syncthreads();

        ull acc2[4][4];
#pragma unroll
        for (int i = 0; i < 4; i++)
#pragma unroll
            for (int j = 0; j < 4; j++) acc2[i][j] = 0ull;

#pragma unroll
        for (int d = 0; d < DH; d++) {
            ull a2[4];
#pragma unroll
            for (int i = 0; i < 4; i++) {
                float a = qu[(tq + i) * 33 + d];
                a2[i] = pack2(a, a);
            }
            const float* Kd = KV + d * 260 + 2 * tc2;
#pragma unroll
            for (int j = 0; j < 4; j++) {
                ull b2 = *(const ull*)(Kd + 64 * j);
                acc2[0][j] = fma2(a2[0], b2, acc2[0][j]);
                acc2[1][j] = fma2(a2[1], b2, acc2[1][j]);
                acc2[2][j] = fma2(a2[2], b2, acc2[2][j]);
                acc2[3][j] = fma2(a2[3], b2, acc2[3][j]);
            }
        }

        // epilogue: add P[idx], store raw scores into S
#pragma unroll
        for (int i = 0; i < 4; i++) {
            int q = tq + i;
            const unsigned char* ip = g_idx + ((size_t)(b * LL + q0 + q)) * LL + kc + 2 * tc2;
            const float* Pq = Ps + q * 16;
            float* Sr = S + q * 516 + kc + 2 * tc2;
#pragma unroll
            for (int j = 0; j < 4; j++) {
                unsigned int u2 = *(const unsigned short*)(ip + 64 * j);
                float2 s2 = unpack2(acc2[i][j]);
                float2 o;
                o.x = s2.x + Pq[u2 & 255];
                o.y = s2.y + Pq[(u2 >> 8) & 255];
                *(float2*)(Sr + 64 * j) = o;
            }
        }
    }
    __syncthreads();

    // -------- phase 2: softmax rows --------
    {
        const int w = t >> 5, lane = t & 31;
#pragma unroll
        for (int rr = 0; rr < 4; rr++) {
            int r = w * 4 + rr;
            float* Sr = S + r * 516;
            float m = -3.4e38f;
            for (int c = lane; c < LL; c += 32) m = fmaxf(m, Sr[c]);
#pragma unroll
            for (int o = 16; o; o >>= 1) m = fmaxf(m, __shfl_xor_sync(0xffffffffu, m, o));
            float s = 0.0f;
            for (int c = lane; c < LL; c += 32) {
                float e = __expf(Sr[c] - m);
                Sr[c] = e;
                s += e;
            }
#pragma unroll
            for (int o = 16; o; o >>= 1) s += __shfl_xor_sync(0xffffffffu, s, o);
            if (lane == 0) invp[r] = 1.0f / s;
        }
    }
    __syncthreads();

    // write normalized attn
    float* arow = attn + ((size_t)(bh * LL + q0)) * LL;
    for (int i = t; i < 32 * 128; i += 256) {
        int r = i >> 7, c4 = (i & 127) << 2;
        float iv = invp[r];
        float4 e = *(const float4*)(S + r * 516 + c4);
        float4 o = make_float4(e.x * iv, e.y * iv, e.z * iv, e.w * iv);
        *(float4*)(arow + r * LL + c4) = o;
    }

    // -------- phase 3: ctx = S @ V, 4-way k-split, thread = 2q x 8d --------
    const int g  = t >> 6;             // k-slice group (warp-pair uniform)
    const int tg = t & 63;
    const int qp = tg >> 2;            // 0..15 -> q rows 2qp, 2qp+1
    const int dc = (tg & 3) * 8;       // d base
    float* Vs  = KV;                   // [128][36]
    float* red = KV + 4608;            // [4][1060]: g*1060 + q*33 + d

    ull acc[2][4];
#pragma unroll
    for (int i = 0; i < 2; i++)
#pragma unroll
        for (int j = 0; j < 4; j++) acc[i][j] = 0ull;

    for (int kc = 0; kc < LL; kc += 128) {
        __syncthreads();
        for (int i = t; i < 1024; i += 256) {
            int k = i >> 3, dd = (i & 7) * 4;
            *(float4*)(Vs + k * 36 + dd) =
                *(const float4*)(g_v + ((size_t)bh * LL + kc + k) * DH + dd);
        }
        __syncthreads();
        const float* S0 = S + (2 * qp) * 516 + kc + g * 32;
        const float* S1 = S0 + 516;
        const float* Vb = Vs + g * 32 * 36 + dc;
#pragma unroll 8
        for (int kk = 0; kk < 32; kk++) {
            float p0 = S0[kk], p1 = S1[kk];
            ull a0 = pack2(p0, p0);
            ull a1 = pack2(p1, p1);
            const float* Vr = Vb + kk * 36;
            ull b0 = *(const ull*)(Vr);
            ull b1 = *(const ull*)(Vr + 2);
            ull b2 = *(const ull*)(Vr + 4);
            ull b3 = *(const ull*)(Vr + 6);
            acc[0][0] = fma2(a0, b0, acc[0][0]);
            acc[0][1] = fma2(a0, b1, acc[0][1]);
            acc[0][2] = fma2(a0, b2, acc[0][2]);
            acc[0][3] = fma2(a0, b3, acc[0][3]);
            acc[1][0] = fma2(a1, b0, acc[1][0]);
            acc[1][1] = fma2(a1, b1, acc[1][1]);
            acc[1][2] = fma2(a1, b2, acc[1][2]);
            acc[1][3] = fma2(a1, b3, acc[1][3]);
        }
    }
    // write partial sums (red disjoint from Vs; own region per thread)
#pragma unroll
    for (int i = 0; i < 2; i++) {
        int q = 2 * qp + i;
        float* rp = red + g * 1060 + q * 33 + dc;
        float2 c0 = unpack2(acc[i][0]);
        float2 c1 = unpack2(acc[i][1]);
        float2 c2 = unpack2(acc[i][2]);
        float2 c3 = unpack2(acc[i][3]);
        rp[0] = c0.x; rp[1] = c0.y;
        rp[2] = c1.x; rp[3] = c1.y;
        rp[4] = c2.x; rp[5] = c2.y;
        rp[6] = c3.x; rp[7] = c3.y;
    }
    __syncthreads();
    {
        int q = t >> 3, d4 = (t & 7) * 4;
        float iv = invp[q];
        float o[4];
#pragma unroll
        for (int j = 0; j < 4; j++) {
            int off = q * 33 + d4 + j;
            o[j] = red[off] + red[1060 + off] + red[2120 + off] + red[3180 + off];
        }
        float4 ov = make_float4(o[0] * iv, o[1] * iv, o[2] * iv, o[3] * iv);
        *(float4*)(g_ctx + ((size_t)(b * LL) + q0 + q) * DD + h * DH + d4) = ov;
    }
}

// ---------------- kernel 3: output GEMM ctx @ Wo + bo (f32x2) ----------------
__global__ __launch_bounds__(256) void out_gemm_kernel(
        const float* __restrict__ Wo,
        const float* __restrict__ bo,
        float* __restrict__ out) {
    __shared__ float AsT[64 * 66];
    __shared__ float Bs[64 * 68];

    const int t = threadIdx.x;
    const int tr = (t >> 4) * 4;
    const int tc = (t & 15) * 4;
    const int rowBase = blockIdx.y * 64;
    const int colBase = blockIdx.x * 64;

    ull acc2[2][4];
#pragma unroll
    for (int p = 0; p < 2; p++)
#pragma unroll
        for (int j = 0; j < 4; j++) acc2[p][j] = 0ull;

    for (int k0 = 0; k0 < DD; k0 += 64) {
        for (int i = t; i < 1024; i += 256) {
            int m = i >> 4, k4 = (i & 15) * 4;
            float4 x = *(const float4*)(g_ctx + (rowBase + m) * DD + k0 + k4);
            AsT[(k4 + 0) * 66 + m] = x.x;
            AsT[(k4 + 1) * 66 + m] = x.y;
            AsT[(k4 + 2) * 66 + m] = x.z;
            AsT[(k4 + 3) * 66 + m] = x.w;
        }
        for (int i = t; i < 1024; i += 256) {
            int k = i >> 4, n4 = (i & 15) * 4;
            *(float4*)(Bs + k * 68 + n4) = *(const float4*)(Wo + (k0 + k) * DD + colBase + n4);
        }
        __syncthreads();
#pragma unroll 16
        for (int kk = 0; kk < 64; kk++) {
            ull a0 = *(const ull*)(AsT + kk * 66 + tr);
            ull a1 = *(const ull*)(AsT + kk * 66 + tr + 2);
            float4 b4 = *(const float4*)(Bs + kk * 68 + tc);
            ull b0 = pack2(b4.x, b4.x);
            ull b1 = pack2(b4.y, b4.y);
            ull b2 = pack2(b4.z, b4.z);
            ull b3 = pack2(b4.w, b4.w);
            acc2[0][0] = fma2(a0, b0, acc2[0][0]);
            acc2[0][1] = fma2(a0, b1, acc2[0][1]);
            acc2[0][2] = fma2(a0, b2, acc2[0][2]);
            acc2[0][3] = fma2(a0, b3, acc2[0][3]);
            acc2[1][0] = fma2(a1, b0, acc2[1][0]);
            acc2[1][1] = fma2(a1, b1, acc2[1][1]);
            acc2[1][2] = fma2(a1, b2, acc2[1][2]);
            acc2[1][3] = fma2(a1, b3, acc2[1][3]);
        }
        __syncthreads();
    }

    const int col0 = colBase + tc;
    const float4 bi = *(const float4*)(bo + col0);
#pragma unroll
    for (int p = 0; p < 2; p++) {
        float2 c0 = unpack2(acc2[p][0]);
        float2 c1 = unpack2(acc2[p][1]);
        float2 c2 = unpack2(acc2[p][2]);
        float2 c3 = unpack2(acc2[p][3]);
#pragma unroll
        for (int s = 0; s < 2; s++) {
            int row = rowBase + tr + p * 2 + s;
            float4 o;
            o.x = (s ? c0.y : c0.x) + bi.x;
            o.y = (s ? c1.y : c1.x) + bi.y;
            o.z = (s ? c2.y : c2.x) + bi.z;
            o.w = (s ? c3.y : c3.x) + bi.w;
            *(float4*)(out + row * DD + col0) = o;
        }
    }
}

// ---------------- launch ----------------
extern "C" void kernel_launch(void* const* d_in, const int* in_sizes, int n_in,
                              void* d_out, int out_size) {
    const float* X         = (const float*)d_in[0];
    const void*  mask      = d_in[1];
    const int*   distances = (const int*)d_in[2];
    const float* Wq        = (const float*)d_in[3];
    const float* bq        = (const float*)d_in[4];
    const float* Wk        = (const float*)d_in[5];
    const float* bk        = (const float*)d_in[6];
    const float* Wv        = (const float*)d_in[7];
    const float* bv        = (const float*)d_in[8];
    const float* Wo        = (const float*)d_in[9];
    const float* bo        = (const float*)d_in[10];
    const float* rel_table = (const float*)d_in[11];
    const float* uvec      = (const float*)d_in[12];
    const float* vvec      = (const float*)d_in[13];

    float* out  = (float*)d_out;                       // (B,L,D)
    float* attn = (float*)d_out + BB * LL * DD;        // (B,H,L,L)

    const int attn_smem = (32 * 516 + KV_FLOATS + 32 * 33 + 32 * 16 + 32) * 4;
    static int smem_set = 0;
    if (!smem_set) {
        cudaFuncSetAttribute(attn_kernel,
                             cudaFuncAttributeMaxDynamicSharedMemorySize,
                             attn_smem);
        smem_set = 1;
    }

    detect_mask_kernel<<<1, 256>>>((const unsigned int*)mask);
    prep_idx_kernel<<<1024, 256>>>(mask, distances);
    qkv_gemm_kernel<<<dim3(4, 32, 3), 256>>>(X, Wq, bq, Wk, bk, Wv, bv);
    attn_kernel<<<dim3(16, 32), 256, attn_smem>>>(uvec, vvec, rel_table, attn);
    out_gemm_kernel<<<dim3(4, 32), 256>>>(Wo, bo, out);
}

// round 6
// speedup vs baseline: 1.2147x; 1.0729x over previous
#include <cuda_runtime.h>
#include <cuda_bf16.h>

// Problem constants
#define BB 4
#define LL 512
#define DD 256
#define HH 8
#define DH 32
#define QK_SCALE 0.17677669529663687f  // 1/sqrt(32)

typedef unsigned long long ull;
typedef unsigned int uint32;

// ---------------- f32x2 packed-pair helpers (Blackwell FFMA2) ----------------
__device__ __forceinline__ ull pack2(float x, float y) {
    ull d; asm("mov.b64 %0, {%1, %2};" : "=l"(d) : "f"(x), "f"(y)); return d;
}
__device__ __forceinline__ float2 unpack2(ull v) {
    float2 r; asm("mov.b64 {%0, %1}, %2;" : "=f"(r.x), "=f"(r.y) : "l"(v)); return r;
}
__device__ __forceinline__ ull fma2(ull a, ull b, ull c) {
    ull d; asm("fma.rn.f32x2 %0, %1, %2, %3;" : "=l"(d) : "l"(a), "l"(b), "l"(c)); return d;
}

// ---------------- tf32 mma helpers ----------------
__device__ __forceinline__ void mma_tf32(float* c, const uint32* a, uint32 b0, uint32 b1) {
    asm volatile(
        "mma.sync.aligned.m16n8k8.row.col.f32.tf32.tf32.f32 "
        "{%0,%1,%2,%3}, {%4,%5,%6,%7}, {%8,%9}, {%0,%1,%2,%3};"
        : "+f"(c[0]), "+f"(c[1]), "+f"(c[2]), "+f"(c[3])
        : "r"(a[0]), "r"(a[1]), "r"(a[2]), "r"(a[3]), "r"(b0), "r"(b1));
}
__device__ __forceinline__ uint32 cvt_tf32(float f) {
    uint32 u; asm("cvt.rna.tf32.f32 %0, %1;" : "=r"(u) : "f"(f)); return u;
}

// ---------------- device scratch ----------------
__device__ float g_q[BB * HH * LL * DH];   // scaled q, (B,H,L,DH)
__device__ float g_k[BB * HH * LL * DH];
__device__ float g_v[BB * HH * LL * DH];
__device__ float g_ctx[BB * LL * DD];      // ctx in (B,L,D) layout
__device__ unsigned char g_idx[BB * LL * LL]; // fused mask+distance bucket index
__device__ int   g_mask_kind;              // 0=int32, 1=float32, 2=bytes

// ---------------- mask dtype detector ----------------
__global__ void detect_mask_kernel(const unsigned int* mw) {
    __shared__ int flags[2];
    if (threadIdx.x < 2) flags[threadIdx.x] = 0;
    __syncthreads();
    int f1 = 0, f2 = 0;
    for (int i = threadIdx.x; i < 4096; i += blockDim.x) {
        unsigned int w = mw[i];
        if (w == 0u || w == 1u) continue;
        if (w == 0x3F800000u) { f1 = 1; continue; }
        f2 = 1;
    }
    if (f1) atomicOr(&flags[0], 1);
    if (f2) atomicOr(&flags[1], 1);
    __syncthreads();
    if (threadIdx.x == 0)
        g_mask_kind = flags[1] ? 2 : (flags[0] ? 1 : 0);
}

// ---------------- prep: idx = mask ? 12 : dist (bytes) ----------------
__global__ void prep_idx_kernel(const void* __restrict__ mask,
                                const int* __restrict__ dist) {
    const int kind = g_mask_kind;
    const int i = blockIdx.x * 256 + threadIdx.x;      // over 1M/4
    int4 d4 = ((const int4*)dist)[i];
    int m0, m1, m2, m3;
    if (kind == 2) {
        uchar4 m = ((const uchar4*)mask)[i];
        m0 = m.x; m1 = m.y; m2 = m.z; m3 = m.w;
    } else if (kind == 1) {
        float4 m = ((const float4*)mask)[i];
        m0 = (m.x != 0.0f); m1 = (m.y != 0.0f); m2 = (m.z != 0.0f); m3 = (m.w != 0.0f);
    } else {
        int4 m = ((const int4*)mask)[i];
        m0 = m.x; m1 = m.y; m2 = m.z; m3 = m.w;
    }
    uchar4 o;
    o.x = m0 ? 12 : (unsigned char)d4.x;
    o.y = m1 ? 12 : (unsigned char)d4.y;
    o.z = m2 ? 12 : (unsigned char)d4.z;
    o.w = m3 ? 12 : (unsigned char)d4.w;
    ((uchar4*)g_idx)[i] = o;
}

// ---------------- kernel 1: fused QKV projection GEMM (f32x2) ----------------
__global__ __launch_bounds__(256) void qkv_gemm_kernel(
        const float* __restrict__ X,
        const float* __restrict__ Wq, const float* __restrict__ bq,
        const float* __restrict__ Wk, const float* __restrict__ bk,
        const float* __restrict__ Wv, const float* __restrict__ bv) {
    const int z = blockIdx.z;
    const float* W    = (z == 0) ? Wq : (z == 1 ? Wk : Wv);
    const float* bias = (z == 0) ? bq : (z == 1 ? bk : bv);
    float* out        = (z == 0) ? g_q : (z == 1 ? g_k : g_v);
    const float scale = (z == 0) ? QK_SCALE : 1.0f;

    __shared__ float AsT[64 * 66];   // [k][m] transposed
    __shared__ float Bs[64 * 68];    // [k][n]

    const int t = threadIdx.x;
    const int tr = (t >> 4) * 4;
    const int tc = (t & 15) * 4;
    const int rowBase = blockIdx.y * 64;
    const int colBase = blockIdx.x * 64;

    ull acc2[2][4];
#pragma unroll
    for (int p = 0; p < 2; p++)
#pragma unroll
        for (int j = 0; j < 4; j++) acc2[p][j] = 0ull;

    for (int k0 = 0; k0 < DD; k0 += 64) {
        for (int i = t; i < 1024; i += 256) {
            int m = i >> 4, k4 = (i & 15) * 4;
            float4 x = *(const float4*)(X + (rowBase + m) * DD + k0 + k4);
            AsT[(k4 + 0) * 66 + m] = x.x;
            AsT[(k4 + 1) * 66 + m] = x.y;
            AsT[(k4 + 2) * 66 + m] = x.z;
            AsT[(k4 + 3) * 66 + m] = x.w;
        }
        for (int i = t; i < 1024; i += 256) {
            int k = i >> 4, n4 = (i & 15) * 4;
            *(float4*)(Bs + k * 68 + n4) = *(const float4*)(W + (k0 + k) * DD + colBase + n4);
        }
        __syncthreads();
#pragma unroll 16
        for (int kk = 0; kk < 64; kk++) {
            ull a0 = *(const ull*)(AsT + kk * 66 + tr);
            ull a1 = *(const ull*)(AsT + kk * 66 + tr + 2);
            float4 b4 = *(const float4*)(Bs + kk * 68 + tc);
            ull b0 = pack2(b4.x, b4.x);
            ull b1 = pack2(b4.y, b4.y);
            ull b2 = pack2(b4.z, b4.z);
            ull b3 = pack2(b4.w, b4.w);
            acc2[0][0] = fma2(a0, b0, acc2[0][0]);
            acc2[0][1] = fma2(a0, b1, acc2[0][1]);
            acc2[0][2] = fma2(a0, b2, acc2[0][2]);
            acc2[0][3] = fma2(a0, b3, acc2[0][3]);
            acc2[1][0] = fma2(a1, b0, acc2[1][0]);
            acc2[1][1] = fma2(a1, b1, acc2[1][1]);
            acc2[1][2] = fma2(a1, b2, acc2[1][2]);
            acc2[1][3] = fma2(a1, b3, acc2[1][3]);
        }
        __syncthreads();
    }

    const int col0 = colBase + tc;
    const int h = col0 >> 5, d = col0 & 31;
    const float4 bi = *(const float4*)(bias + col0);
#pragma unroll
    for (int p = 0; p < 2; p++) {
        float2 c0 = unpack2(acc2[p][0]);
        float2 c1 = unpack2(acc2[p][1]);
        float2 c2 = unpack2(acc2[p][2]);
        float2 c3 = unpack2(acc2[p][3]);
#pragma unroll
        for (int s = 0; s < 2; s++) {
            int row = rowBase + tr + p * 2 + s;
            int b = row >> 9, l = row & 511;
            float4 o;
            o.x = ((s ? c0.y : c0.x) + bi.x) * scale;
            o.y = ((s ? c1.y : c1.x) + bi.y) * scale;
            o.z = ((s ? c2.y : c2.x) + bi.z) * scale;
            o.w = ((s ? c3.y : c3.x) + bi.w) * scale;
            *(float4*)(out + (((b * HH + h) * LL) + l) * DH + d) = o;
        }
    }
}

// ---------------- kernel 2: fully fused attention (tf32 mma) ----------------
// smem floats: S 16512 | KV 8960 | qu 1056 | Ps 512 | invp 32
//   KV union: KsT[32][260]=8320 (scores) ; Vs[128][36]=4608 + red 4x1088=4352 (ctx) ; tbl 396
#define KV_FLOATS 8960
__global__ __launch_bounds__(256, 2) void attn_kernel(
        const float* __restrict__ uvec,
        const float* __restrict__ vvec,
        const float* __restrict__ rel_table,
        float* __restrict__ attn) {
    extern __shared__ float sm[];
    float* S    = sm;                  // [32][516] scores/exp
    float* KV   = S + 32 * 516;
    float* qu   = KV + KV_FLOATS;      // [32][33]
    float* Ps   = qu + 32 * 33;        // [32][16]
    float* invp = Ps + 32 * 16;        // [32]

    const int bh = blockIdx.y;
    const int b = bh >> 3, h = bh & 7;
    const int q0 = blockIdx.x * 32;
    const int t = threadIdx.x;
    const int w = t >> 5;
    const int lane = t & 31;
    const int lq = lane >> 2;          // 0..7
    const int lc = lane & 3;           // 0..3

    // -------- phase 0: qu = q+v, table slice, P --------
    {
        int q = t >> 3, d4 = (t & 7) * 4;
        float4 qv = *(const float4*)(g_q + ((size_t)bh * LL + q0 + q) * DH + d4);
        float4 vv = *(const float4*)(vvec + h * DH + d4);
        qu[q * 33 + d4 + 0] = qv.x + vv.x;
        qu[q * 33 + d4 + 1] = qv.y + vv.y;
        qu[q * 33 + d4 + 2] = qv.z + vv.z;
        qu[q * 33 + d4 + 3] = qv.w + vv.w;
    }
    float* tbl = KV;   // [12][33]
    for (int i = t; i < 384; i += 256) {
        int bu = i >> 5, d = i & 31;
        tbl[bu * 33 + d] = rel_table[bu * DD + h * DH + d];
    }
    __syncthreads();
    for (int j = t; j < 384; j += 256) {
        int q = j / 12, bu = j - q * 12;
        const float* qp = qu + q * 33;
        const float* tp = tbl + bu * 33;
        float s = 0.0f;
#pragma unroll
        for (int d = 0; d < 32; d++) s = fmaf(qp[d], tp[d], s);
        Ps[q * 16 + bu] = s;
    }
    if (t < 32) Ps[t * 16 + 12] = -1e18f;
    __syncthreads();
    // qu: (q+v) -> (q+u)
    {
        int q = t >> 3, d4 = (t & 7) * 4;
        float4 uu = *(const float4*)(uvec + h * DH + d4);
        float4 vv = *(const float4*)(vvec + h * DH + d4);
        qu[q * 33 + d4 + 0] += uu.x - vv.x;
        qu[q * 33 + d4 + 1] += uu.y - vv.y;
        qu[q * 33 + d4 + 2] += uu.z - vv.z;
        qu[q * 33 + d4 + 3] += uu.w - vv.w;
    }

    // -------- phase 1: scores via tf32 mma (m16n8k8) --------
    // per warp: n-cols [w*32, w*32+32) within each 256-k chunk, m = all 32 q.
    for (int kc = 0; kc < LL; kc += 256) {
        __syncthreads();
        // load K chunk transposed: KsT[d][k], stride 260
        for (int i = t; i < 2048; i += 256) {
            int k = i >> 3, d4 = (i & 7) * 4;
            float4 kv = *(const float4*)(g_k + ((size_t)bh * LL + kc + k) * DH + d4);
            KV[(d4 + 0) * 260 + k] = kv.x;
            KV[(d4 + 1) * 260 + k] = kv.y;
            KV[(d4 + 2) * 260 + k] = kv.z;
            KV[(d4 + 3) * 260 + k] = kv.w;
        }
        __syncthreads();

        float c[2][4][4];
#pragma unroll
        for (int mt = 0; mt < 2; mt++)
#pragma unroll
            for (int nt = 0; nt < 4; nt++)
#pragma unroll
                for (int e = 0; e < 4; e++) c[mt][nt][e] = 0.0f;

#pragma unroll
        for (int ks = 0; ks < 4; ks++) {
            uint32 a[2][4];
#pragma unroll
            for (int mt = 0; mt < 2; mt++) {
                const float* ab = qu + (mt * 16 + lq) * 33 + ks * 8 + lc;
                a[mt][0] = __float_as_uint(ab[0]);
                a[mt][1] = __float_as_uint(ab[8 * 33]);
                a[mt][2] = __float_as_uint(ab[4]);
                a[mt][3] = __float_as_uint(ab[8 * 33 + 4]);
            }
#pragma unroll
            for (int nt = 0; nt < 4; nt++) {
                int kn = w * 32 + nt * 8 + lq;   // chunk-local k col
                uint32 b0 = __float_as_uint(KV[(ks * 8 + lc) * 260 + kn]);
                uint32 b1 = __float_as_uint(KV[(ks * 8 + lc + 4) * 260 + kn]);
                mma_tf32(c[0][nt], a[0], b0, b1);
                mma_tf32(c[1][nt], a[1], b0, b1);
            }
        }

        // epilogue: add P[idx], store raw scores into S
#pragma unroll
        for (int mt = 0; mt < 2; mt++) {
#pragma unroll
            for (int nt = 0; nt < 4; nt++) {
                int r0 = mt * 16 + lq;
                int kcol = w * 32 + nt * 8 + 2 * lc;  // chunk-local
                int kk = kc + kcol;                    // global k
                const unsigned short* ip0 = (const unsigned short*)
                    (g_idx + ((size_t)(b * LL + q0 + r0)) * LL + kk);
                const unsigned short* ip1 = (const unsigned short*)
                    (g_idx + ((size_t)(b * LL + q0 + r0 + 8)) * LL + kk);
                unsigned int u0 = *ip0, u1 = *ip1;
                const float* P0 = Ps + r0 * 16;
                const float* P1 = Ps + (r0 + 8) * 16;
                float2 o0, o1;
                o0.x = c[mt][nt][0] + P0[u0 & 255];
                o0.y = c[mt][nt][1] + P0[(u0 >> 8) & 255];
                o1.x = c[mt][nt][2] + P1[u1 & 255];
                o1.y = c[mt][nt][3] + P1[(u1 >> 8) & 255];
                *(float2*)(S + r0 * 516 + kk - kc + kc) = o0;  // S[r0*516 + kk]
                *(float2*)(S + (r0 + 8) * 516 + kk) = o1;
            }
        }
    }
    __syncthreads();

    // -------- phase 2: softmax rows --------
    {
#pragma unroll
        for (int rr = 0; rr < 4; rr++) {
            int r = w * 4 + rr;
            float* Sr = S + r * 516;
            float m = -3.4e38f;
            for (int cix = lane; cix < LL; cix += 32) m = fmaxf(m, Sr[cix]);
#pragma unroll
            for (int o = 16; o; o >>= 1) m = fmaxf(m, __shfl_xor_sync(0xffffffffu, m, o));
            float s = 0.0f;
            for (int cix = lane; cix < LL; cix += 32) {
                float e = __expf(Sr[cix] - m);
                Sr[cix] = e;
                s += e;
            }
#pragma unroll
            for (int o = 16; o; o >>= 1) s += __shfl_xor_sync(0xffffffffu, s, o);
            if (lane == 0) invp[r] = 1.0f / s;
        }
    }
    __syncthreads();

    // write normalized attn
    float* arow = attn + ((size_t)(bh * LL + q0)) * LL;
    for (int i = t; i < 32 * 128; i += 256) {
        int r = i >> 7, c4 = (i & 127) << 2;
        float iv = invp[r];
        float4 e = *(const float4*)(S + r * 516 + c4);
        float4 o = make_float4(e.x * iv, e.y * iv, e.z * iv, e.w * iv);
        *(float4*)(arow + r * LL + c4) = o;
    }

    // -------- phase 3: ctx = S @ V via tf32 mma, per-warp k-slices --------
    float* Vs  = KV;                   // [128][36]
    float* red = KV + 4608;            // [4][1088]: g*1088 + q*34 + d

    float c[2][4][4];
#pragma unroll
    for (int mt = 0; mt < 2; mt++)
#pragma unroll
        for (int nt = 0; nt < 4; nt++)
#pragma unroll
            for (int e = 0; e < 4; e++) c[mt][nt][e] = 0.0f;

    for (int kc = 0; kc < LL; kc += 128) {
        __syncthreads();
        for (int i = t; i < 1024; i += 256) {
            int k = i >> 3, dd = (i & 7) * 4;
            *(float4*)(Vs + k * 36 + dd) =
                *(const float4*)(g_v + ((size_t)bh * LL + kc + k) * DH + dd);
        }
        __syncthreads();
#pragma unroll
        for (int ks = 0; ks < 2; ks++) {
            int kb = w * 16 + ks * 8;       // chunk-local k base for this warp
            uint32 a[2][4];
#pragma unroll
            for (int mt = 0; mt < 2; mt++) {
                const float* ab = S + (mt * 16 + lq) * 516 + kc + kb + lc;
                a[mt][0] = cvt_tf32(ab[0]);
                a[mt][1] = cvt_tf32(ab[8 * 516]);
                a[mt][2] = cvt_tf32(ab[4]);
                a[mt][3] = cvt_tf32(ab[8 * 516 + 4]);
            }
#pragma unroll
            for (int nt = 0; nt < 4; nt++) {
                int dn = nt * 8 + lq;
                uint32 b0 = __float_as_uint(Vs[(kb + lc) * 36 + dn]);
                uint32 b1 = __float_as_uint(Vs[(kb + lc + 4) * 36 + dn]);
                mma_tf32(c[0][nt], a[0], b0, b1);
                mma_tf32(c[1][nt], a[1], b0, b1);
            }
        }
    }
    __syncthreads();   // done reading Vs; red region reuse is disjoint but sync for S? not needed; keep for safety

    // two-stage cross-warp reduction
    if (w >= 4) {
        float* rg = red + (w - 4) * 1088;
#pragma unroll
        for (int mt = 0; mt < 2; mt++)
#pragma unroll
            for (int nt = 0; nt < 4; nt++) {
                int r0 = mt * 16 + lq, dc = nt * 8 + 2 * lc;
                *(float2*)(rg + r0 * 34 + dc) = make_float2(c[mt][nt][0], c[mt][nt][1]);
                *(float2*)(rg + (r0 + 8) * 34 + dc) = make_float2(c[mt][nt][2], c[mt][nt][3]);
            }
    }
    __syncthreads();
    if (w < 4) {
        float* rg = red + w * 1088;
#pragma unroll
        for (int mt = 0; mt < 2; mt++)
#pragma unroll
            for (int nt = 0; nt < 4; nt++) {
                int r0 = mt * 16 + lq, dc = nt * 8 + 2 * lc;
                float2 p0 = *(const float2*)(rg + r0 * 34 + dc);
                float2 p1 = *(const float2*)(rg + (r0 + 8) * 34 + dc);
                *(float2*)(rg + r0 * 34 + dc) =
                    make_float2(c[mt][nt][0] + p0.x, c[mt][nt][1] + p0.y);
                *(float2*)(rg + (r0 + 8) * 34 + dc) =
                    make_float2(c[mt][nt][2] + p1.x, c[mt][nt][3] + p1.y);
            }
    }
    __syncthreads();
    {
        int q = t >> 3, d4 = (t & 7) * 4;
        float iv = invp[q];
        float o[4];
#pragma unroll
        for (int j = 0; j < 4; j++) {
            int off = q * 34 + d4 + j;
            o[j] = red[off] + red[1088 + off] + red[2176 + off] + red[3264 + off];
        }
        float4 ov = make_float4(o[0] * iv, o[1] * iv, o[2] * iv, o[3] * iv);
        *(float4*)(g_ctx + ((size_t)(b * LL) + q0 + q) * DD + h * DH + d4) = ov;
    }
}

// ---------------- kernel 3: output GEMM ctx @ Wo + bo (f32x2) ----------------
__global__ __launch_bounds__(256) void out_gemm_kernel(
        const float* __restrict__ Wo,
        const float* __restrict__ bo,
        float* __restrict__ out) {
    __shared__ float AsT[64 * 66];
    __shared__ float Bs[64 * 68];

    const int t = threadIdx.x;
    const int tr = (t >> 4) * 4;
    const int tc = (t & 15) * 4;
    const int rowBase = blockIdx.y * 64;
    const int colBase = blockIdx.x * 64;

    ull acc2[2][4];
#pragma unroll
    for (int p = 0; p < 2; p++)
#pragma unroll
        for (int j = 0; j < 4; j++) acc2[p][j] = 0ull;

    for (int k0 = 0; k0 < DD; k0 += 64) {
        for (int i = t; i < 1024; i += 256) {
            int m = i >> 4, k4 = (i & 15) * 4;
            float4 x = *(const float4*)(g_ctx + (rowBase + m) * DD + k0 + k4);
            AsT[(k4 + 0) * 66 + m] = x.x;
            AsT[(k4 + 1) * 66 + m] = x.y;
            AsT[(k4 + 2) * 66 + m] = x.z;
            AsT[(k4 + 3) * 66 + m] = x.w;
        }
        for (int i = t; i < 1024; i += 256) {
            int k = i >> 4, n4 = (i & 15) * 4;
            *(float4*)(Bs + k * 68 + n4) = *(const float4*)(Wo + (k0 + k) * DD + colBase + n4);
        }
        __syncthreads();
#pragma unroll 16
        for (int kk = 0; kk < 64; kk++) {
            ull a0 = *(const ull*)(AsT + kk * 66 + tr);
            ull a1 = *(const ull*)(AsT + kk * 66 + tr + 2);
            float4 b4 = *(const float4*)(Bs + kk * 68 + tc);
            ull b0 = pack2(b4.x, b4.x);
            ull b1 = pack2(b4.y, b4.y);
            ull b2 = pack2(b4.z, b4.z);
            ull b3 = pack2(b4.w, b4.w);
            acc2[0][0] = fma2(a0, b0, acc2[0][0]);
            acc2[0][1] = fma2(a0, b1, acc2[0][1]);
            acc2[0][2] = fma2(a0, b2, acc2[0][2]);
            acc2[0][3] = fma2(a0, b3, acc2[0][3]);
            acc2[1][0] = fma2(a1, b0, acc2[1][0]);
            acc2[1][1] = fma2(a1, b1, acc2[1][1]);
            acc2[1][2] = fma2(a1, b2, acc2[1][2]);
            acc2[1][3] = fma2(a1, b3, acc2[1][3]);
        }
        __syncthreads();
    }

    const int col0 = colBase + tc;
    const float4 bi = *(const float4*)(bo + col0);
#pragma unroll
    for (int p = 0; p < 2; p++) {
        float2 c0 = unpack2(acc2[p][0]);
        float2 c1 = unpack2(acc2[p][1]);
        float2 c2 = unpack2(acc2[p][2]);
        float2 c3 = unpack2(acc2[p][3]);
#pragma unroll
        for (int s = 0; s < 2; s++) {
            int row = rowBase + tr + p * 2 + s;
            float4 o;
            o.x = (s ? c0.y : c0.x) + bi.x;
            o.y = (s ? c1.y : c1.x) + bi.y;
            o.z = (s ? c2.y : c2.x) + bi.z;
            o.w = (s ? c3.y : c3.x) + bi.w;
            *(float4*)(out + row * DD + col0) = o;
        }
    }
}

// ---------------- launch ----------------
extern "C" void kernel_launch(void* const* d_in, const int* in_sizes, int n_in,
                              void* d_out, int out_size) {
    const float* X         = (const float*)d_in[0];
    const void*  mask      = d_in[1];
    const int*   distances = (const int*)d_in[2];
    const float* Wq        = (const float*)d_in[3];
    const float* bq        = (const float*)d_in[4];
    const float* Wk        = (const float*)d_in[5];
    const float* bk        = (const float*)d_in[6];
    const float* Wv        = (const float*)d_in[7];
    const float* bv        = (const float*)d_in[8];
    const float* Wo        = (const float*)d_in[9];
    const float* bo        = (const float*)d_in[10];
    const float* rel_table = (const float*)d_in[11];
    const float* uvec      = (const float*)d_in[12];
    const float* vvec      = (const float*)d_in[13];

    float* out  = (float*)d_out;                       // (B,L,D)
    float* attn = (float*)d_out + BB * LL * DD;        // (B,H,L,L)

    const int attn_smem = (32 * 516 + KV_FLOATS + 32 * 33 + 32 * 16 + 32) * 4;
    static int smem_set = 0;
    if (!smem_set) {
        cudaFuncSetAttribute(attn_kernel,
                             cudaFuncAttributeMaxDynamicSharedMemorySize,
                             attn_smem);
        smem_set = 1;
    }

    detect_mask_kernel<<<1, 256>>>((const unsigned int*)mask);
    prep_idx_kernel<<<1024, 256>>>(mask, distances);
    qkv_gemm_kernel<<<dim3(4, 32, 3), 256>>>(X, Wq, bq, Wk, bk, Wv, bv);
    attn_kernel<<<dim3(16, 32), 256, attn_smem>>>(uvec, vvec, rel_table, attn);
    out_gemm_kernel<<<dim3(4, 32), 256>>>(Wo, bo, out);
}

// round 8
// speedup vs baseline: 1.3424x; 1.1052x over previous
#include <cuda_runtime.h>
#include <cuda_bf16.h>

// Problem constants
#define BB 4
#define LL 512
#define DD 256
#define HH 8
#define DH 32
#define QK_SCALE 0.17677669529663687f  // 1/sqrt(32)

typedef unsigned long long ull;
typedef unsigned int uint32;

// ---------------- tf32 mma helpers ----------------
__device__ __forceinline__ void mma_tf32(float* c, const uint32* a, uint32 b0, uint32 b1) {
    asm volatile(
        "mma.sync.aligned.m16n8k8.row.col.f32.tf32.tf32.f32 "
        "{%0,%1,%2,%3}, {%4,%5,%6,%7}, {%8,%9}, {%0,%1,%2,%3};"
        : "+f"(c[0]), "+f"(c[1]), "+f"(c[2]), "+f"(c[3])
        : "r"(a[0]), "r"(a[1]), "r"(a[2]), "r"(a[3]), "r"(b0), "r"(b1));
}
__device__ __forceinline__ uint32 cvt_tf32(float f) {
    uint32 u; asm("cvt.rna.tf32.f32 %0, %1;" : "=r"(u) : "f"(f)); return u;
}

// ---------------- cp.async helpers ----------------
__device__ __forceinline__ void cp_async16(uint32 s, const void* g) {
    asm volatile("cp.async.cg.shared.global [%0], [%1], 16;" :: "r"(s), "l"(g));
}
__device__ __forceinline__ void cp_commit() {
    asm volatile("cp.async.commit_group;");
}
template <int N>
__device__ __forceinline__ void cp_wait() {
    asm volatile("cp.async.wait_group %0;" :: "n"(N));
}

// ---------------- device scratch ----------------
__device__ float g_q[BB * HH * LL * DH];   // scaled q, (B,H,L,DH)
__device__ float g_k[BB * HH * LL * DH];
__device__ float g_v[BB * HH * LL * DH];
__device__ float g_ctx[BB * LL * DD];      // ctx in (B,L,D) layout
__device__ unsigned char g_idx[BB * LL * LL]; // fused mask+distance bucket index
__device__ int   g_mask_kind;              // 0=int32, 1=float32, 2=bytes

// ---------------- mask dtype detector ----------------
__global__ void detect_mask_kernel(const unsigned int* mw) {
    __shared__ int flags[2];
    if (threadIdx.x < 2) flags[threadIdx.x] = 0;
    __syncthreads();
    int f1 = 0, f2 = 0;
    for (int i = threadIdx.x; i < 4096; i += blockDim.x) {
        unsigned int w = mw[i];
        if (w == 0u || w == 1u) continue;
        if (w == 0x3F800000u) { f1 = 1; continue; }
        f2 = 1;
    }
    if (f1) atomicOr(&flags[0], 1);
    if (f2) atomicOr(&flags[1], 1);
    __syncthreads();
    if (threadIdx.x == 0)
        g_mask_kind = flags[1] ? 2 : (flags[0] ? 1 : 0);
}

// ---------------- prep: idx = mask ? 12 : dist (bytes) ----------------
__global__ void prep_idx_kernel(const void* __restrict__ mask,
                                const int* __restrict__ dist) {
    const int kind = g_mask_kind;
    const int i = blockIdx.x * 256 + threadIdx.x;
    int4 d4 = ((const int4*)dist)[i];
    int m0, m1, m2, m3;
    if (kind == 2) {
        uchar4 m = ((const uchar4*)mask)[i];
        m0 = m.x; m1 = m.y; m2 = m.z; m3 = m.w;
    } else if (kind == 1) {
        float4 m = ((const float4*)mask)[i];
        m0 = (m.x != 0.0f); m1 = (m.y != 0.0f); m2 = (m.z != 0.0f); m3 = (m.w != 0.0f);
    } else {
        int4 m = ((const int4*)mask)[i];
        m0 = m.x; m1 = m.y; m2 = m.z; m3 = m.w;
    }
    uchar4 o;
    o.x = m0 ? 12 : (unsigned char)d4.x;
    o.y = m1 ? 12 : (unsigned char)d4.y;
    o.z = m2 ? 12 : (unsigned char)d4.z;
    o.w = m3 ? 12 : (unsigned char)d4.w;
    ((uchar4*)g_idx)[i] = o;
}

// ---------------- kernel 1: fused QKV projection GEMM (tf32, 3-MMA split) ----------------
__global__ __launch_bounds__(256) void qkv_gemm_kernel(
        const float* __restrict__ X,
        const float* __restrict__ Wq, const float* __restrict__ bq,
        const float* __restrict__ Wk, const float* __restrict__ bk,
        const float* __restrict__ Wv, const float* __restrict__ bv) {
    const int z = blockIdx.z;
    const float* W    = (z == 0) ? Wq : (z == 1 ? Wk : Wv);
    const float* bias = (z == 0) ? bq : (z == 1 ? bk : bv);
    float* out        = (z == 0) ? g_q : (z == 1 ? g_k : g_v);
    const float scale = (z == 0) ? QK_SCALE : 1.0f;

    __shared__ float As[64 * 68];    // [m][k]
    __shared__ float Bs[64 * 68];    // [k][n]

    const int t = threadIdx.x;
    const int w = t >> 5, lane = t & 31;
    const int lq = lane >> 2, lc = lane & 3;
    const int wm = w >> 2, wn = w & 3;
    const int rowBase = blockIdx.y * 64;
    const int colBase = blockIdx.x * 64;

    float cc[2][2][4];
#pragma unroll
    for (int mt = 0; mt < 2; mt++)
#pragma unroll
        for (int nt = 0; nt < 2; nt++)
#pragma unroll
            for (int e = 0; e < 4; e++) cc[mt][nt][e] = 0.0f;

    for (int k0 = 0; k0 < DD; k0 += 64) {
        for (int i = t; i < 1024; i += 256) {
            int m = i >> 4, k4 = (i & 15) * 4;
            *(float4*)(As + m * 68 + k4) = *(const float4*)(X + (rowBase + m) * DD + k0 + k4);
        }
        for (int i = t; i < 1024; i += 256) {
            int k = i >> 4, n4 = (i & 15) * 4;
            *(float4*)(Bs + k * 68 + n4) = *(const float4*)(W + (k0 + k) * DD + colBase + n4);
        }
        __syncthreads();
#pragma unroll
        for (int ks = 0; ks < 8; ks++) {
            uint32 ah[2][4], al[2][4];
#pragma unroll
            for (int mt = 0; mt < 2; mt++) {
                const float* ab = As + (wm * 32 + mt * 16 + lq) * 68 + ks * 8 + lc;
                float x0 = ab[0], x1 = ab[8 * 68], x2 = ab[4], x3 = ab[8 * 68 + 4];
                ah[mt][0] = cvt_tf32(x0); al[mt][0] = cvt_tf32(x0 - __uint_as_float(ah[mt][0]));
                ah[mt][1] = cvt_tf32(x1); al[mt][1] = cvt_tf32(x1 - __uint_as_float(ah[mt][1]));
                ah[mt][2] = cvt_tf32(x2); al[mt][2] = cvt_tf32(x2 - __uint_as_float(ah[mt][2]));
                ah[mt][3] = cvt_tf32(x3); al[mt][3] = cvt_tf32(x3 - __uint_as_float(ah[mt][3]));
            }
#pragma unroll
            for (int nt = 0; nt < 2; nt++) {
                const float* bb = Bs + (ks * 8 + lc) * 68 + wn * 16 + nt * 8 + lq;
                float w0 = bb[0], w1 = bb[4 * 68];
                uint32 bh0 = cvt_tf32(w0);
                uint32 bl0 = cvt_tf32(w0 - __uint_as_float(bh0));
                uint32 bh1 = cvt_tf32(w1);
                uint32 bl1 = cvt_tf32(w1 - __uint_as_float(bh1));
                mma_tf32(cc[0][nt], ah[0], bh0, bh1);
                mma_tf32(cc[0][nt], al[0], bh0, bh1);
                mma_tf32(cc[0][nt], ah[0], bl0, bl1);
                mma_tf32(cc[1][nt], ah[1], bh0, bh1);
                mma_tf32(cc[1][nt], al[1], bh0, bh1);
                mma_tf32(cc[1][nt], ah[1], bl0, bl1);
            }
        }
        __syncthreads();
    }

#pragma unroll
    for (int mt = 0; mt < 2; mt++) {
#pragma unroll
        for (int nt = 0; nt < 2; nt++) {
            int col0 = colBase + wn * 16 + nt * 8 + 2 * lc;
            int h = col0 >> 5, d = col0 & 31;
            float bx = bias[col0], by = bias[col0 + 1];
            int r0 = rowBase + wm * 32 + mt * 16 + lq;
            {
                int b = r0 >> 9, l = r0 & 511;
                float2 o = make_float2((cc[mt][nt][0] + bx) * scale,
                                       (cc[mt][nt][1] + by) * scale);
                *(float2*)(out + (((b * HH + h) * LL) + l) * DH + d) = o;
            }
            {
                int r1 = r0 + 8;
                int b = r1 >> 9, l = r1 & 511;
                float2 o = make_float2((cc[mt][nt][2] + bx) * scale,
                                       (cc[mt][nt][3] + by) * scale);
                *(float2*)(out + (((b * HH + h) * LL) + l) * DH + d) = o;
            }
        }
    }
}

// ---------------- kernel 2: fully fused attention (tf32 mma + cp.async pipeline) ----------------
// smem floats: S 16512 | KB0 4608 | KB1 4608 | qu 1056 | Ps 512 | invp 32 = 27328
__global__ __launch_bounds__(256, 2) void attn_kernel(
        const float* __restrict__ uvec,
        const float* __restrict__ vvec,
        const float* __restrict__ rel_table,
        float* __restrict__ attn) {
    extern __shared__ float sm[];
    float* S    = sm;                    // [32][516]
    float* KB0  = sm + 16512;            // [128][36]
    float* KB1  = sm + 21120;            // [128][36]
    float* qu   = sm + 25728;            // [32][33]
    float* Ps   = qu + 1056;             // [32][16]
    float* invp = Ps + 512;              // [32]

    const int bh = blockIdx.y;
    const int b = bh >> 3, h = bh & 7;
    const int q0 = blockIdx.x * 32;
    const int t = threadIdx.x;
    const int w = t >> 5;
    const int lane = t & 31;
    const int lq = lane >> 2;
    const int lc = lane & 3;

    const float* kbase = g_k + (size_t)bh * LL * DH;
    const float* vbase = g_v + (size_t)bh * LL * DH;
    const uint32 sKB0 = (uint32)__cvta_generic_to_shared(KB0);
    const uint32 sKB1 = (uint32)__cvta_generic_to_shared(KB1);

    // prefetch K chunk 0 into KB0
    {
#pragma unroll
        for (int i = 0; i < 4; i++) {
            int idx = t + i * 256;
            int k = idx >> 3, seg = idx & 7;
            cp_async16(sKB0 + k * 144 + seg * 16, kbase + k * 32 + seg * 4);
        }
        cp_commit();
    }

    // -------- phase 0: qu = q+v, table slice (in KB1), P --------
    {
        int q = t >> 3, d4 = (t & 7) * 4;
        float4 qv = *(const float4*)(g_q + ((size_t)bh * LL + q0 + q) * DH + d4);
        float4 vv = *(const float4*)(vvec + h * DH + d4);
        qu[q * 33 + d4 + 0] = qv.x + vv.x;
        qu[q * 33 + d4 + 1] = qv.y + vv.y;
        qu[q * 33 + d4 + 2] = qv.z + vv.z;
        qu[q * 33 + d4 + 3] = qv.w + vv.w;
    }
    float* tbl = KB1;   // [12][33]
    for (int i = t; i < 384; i += 256) {
        int bu = i >> 5, d = i & 31;
        tbl[bu * 33 + d] = rel_table[bu * DD + h * DH + d];
    }
    __syncthreads();
    for (int j = t; j < 384; j += 256) {
        int q = j / 12, bu = j - q * 12;
        const float* qp = qu + q * 33;
        const float* tp = tbl + bu * 33;
        float s = 0.0f;
#pragma unroll
        for (int d = 0; d < 32; d++) s = fmaf(qp[d], tp[d], s);
        Ps[q * 16 + bu] = s;
    }
    if (t < 32) Ps[t * 16 + 12] = -1e18f;
    __syncthreads();
    // qu: (q+v) -> (q+u)
    {
        int q = t >> 3, d4 = (t & 7) * 4;
        float4 uu = *(const float4*)(uvec + h * DH + d4);
        float4 vv = *(const float4*)(vvec + h * DH + d4);
        qu[q * 33 + d4 + 0] += uu.x - vv.x;
        qu[q * 33 + d4 + 1] += uu.y - vv.y;
        qu[q * 33 + d4 + 2] += uu.z - vv.z;
        qu[q * 33 + d4 + 3] += uu.w - vv.w;
    }

    // -------- phase 1: scores via tf32 mma, 4 chunks of 128 k, double-buffered --------
#pragma unroll 1
    for (int c = 0; c < 4; c++) {
        __syncthreads();
        if (c < 3) {
            uint32 dst = ((c + 1) & 1) ? sKB1 : sKB0;
            const float* src = kbase + (c + 1) * 128 * 32;
#pragma unroll
            for (int i = 0; i < 4; i++) {
                int idx = t + i * 256;
                int k = idx >> 3, seg = idx & 7;
                cp_async16(dst + k * 144 + seg * 16, src + k * 32 + seg * 4);
            }
            cp_commit();
        } else {
            // prefetch V chunk 0 into KB0 (K chunk 2 fully consumed)
#pragma unroll
            for (int i = 0; i < 4; i++) {
                int idx = t + i * 256;
                int k = idx >> 3, seg = idx & 7;
                cp_async16(sKB0 + k * 144 + seg * 16, vbase + k * 32 + seg * 4);
            }
            cp_commit();
        }
        cp_wait<1>();
        __syncthreads();

        const float* buf = (c & 1) ? KB1 : KB0;
        float cc[2][2][4];
#pragma unroll
        for (int mt = 0; mt < 2; mt++)
#pragma unroll
            for (int nt = 0; nt < 2; nt++)
#pragma unroll
                for (int e = 0; e < 4; e++) cc[mt][nt][e] = 0.0f;

#pragma unroll
        for (int ks = 0; ks < 4; ks++) {
            uint32 a[2][4];
#pragma unroll
            for (int mt = 0; mt < 2; mt++) {
                const float* ab = qu + (mt * 16 + lq) * 33 + ks * 8 + lc;
                a[mt][0] = __float_as_uint(ab[0]);
                a[mt][1] = __float_as_uint(ab[8 * 33]);
                a[mt][2] = __float_as_uint(ab[4]);
                a[mt][3] = __float_as_uint(ab[8 * 33 + 4]);
            }
#pragma unroll
            for (int nt = 0; nt < 2; nt++) {
                int kn = w * 16 + nt * 8 + lq;
                uint32 b0 = __float_as_uint(buf[kn * 36 + ks * 8 + lc]);
                uint32 b1 = __float_as_uint(buf[kn * 36 + ks * 8 + lc + 4]);
                mma_tf32(cc[0][nt], a[0], b0, b1);
                mma_tf32(cc[1][nt], a[1], b0, b1);
            }
        }

        int kc = c * 128;
#pragma unroll
        for (int mt = 0; mt < 2; mt++) {
#pragma unroll
            for (int nt = 0; nt < 2; nt++) {
                int r0 = mt * 16 + lq;
                int kk = kc + w * 16 + nt * 8 + 2 * lc;
                unsigned int u0 = *(const unsigned short*)
                    (g_idx + ((size_t)(b * LL + q0 + r0)) * LL + kk);
                unsigned int u1 = *(const unsigned short*)
                    (g_idx + ((size_t)(b * LL + q0 + r0 + 8)) * LL + kk);
                const float* P0 = Ps + r0 * 16;
                const float* P1 = Ps + (r0 + 8) * 16;
                float2 o0, o1;
                o0.x = cc[mt][nt][0] + P0[u0 & 255];
                o0.y = cc[mt][nt][1] + P0[(u0 >> 8) & 255];
                o1.x = cc[mt][nt][2] + P1[u1 & 255];
                o1.y = cc[mt][nt][3] + P1[(u1 >> 8) & 255];
                *(float2*)(S + r0 * 516 + kk) = o0;
                *(float2*)(S + (r0 + 8) * 516 + kk) = o1;
            }
        }
    }
    __syncthreads();

    // -------- phase 2: softmax rows (V chunk 0 streaming in behind) --------
    {
#pragma unroll
        for (int rr = 0; rr < 4; rr++) {
            int r = w * 4 + rr;
            float* Sr = S + r * 516;
            float m = -3.4e38f;
            for (int cix = lane; cix < LL; cix += 32) m = fmaxf(m, Sr[cix]);
#pragma unroll
            for (int o = 16; o; o >>= 1) m = fmaxf(m, __shfl_xor_sync(0xffffffffu, m, o));
            float s = 0.0f;
            for (int cix = lane; cix < LL; cix += 32) {
                float e = __expf(Sr[cix] - m);
                Sr[cix] = e;
                s += e;
            }
#pragma unroll
            for (int o = 16; o; o >>= 1) s += __shfl_xor_sync(0xffffffffu, s, o);
            if (lane == 0) invp[r] = 1.0f / s;
        }
    }
    __syncthreads();

    // write normalized attn
    float* arow = attn + ((size_t)(bh * LL + q0)) * LL;
    for (int i = t; i < 32 * 128; i += 256) {
        int r = i >> 7, c4 = (i & 127) << 2;
        float iv = invp[r];
        float4 e = *(const float4*)(S + r * 516 + c4);
        float4 o = make_float4(e.x * iv, e.y * iv, e.z * iv, e.w * iv);
        *(float4*)(arow + r * LL + c4) = o;
    }

    // -------- phase 3: ctx = S @ V via tf32 mma, double-buffered V --------
    float cv[2][4][4];
#pragma unroll
    for (int mt = 0; mt < 2; mt++)
#pragma unroll
        for (int nt = 0; nt < 4; nt++)
#pragma unroll
            for (int e = 0; e < 4; e++) cv[mt][nt][e] = 0.0f;

#pragma unroll 1
    for (int c = 0; c < 4; c++) {
        __syncthreads();
        if (c < 3) {
            uint32 dst = ((c + 1) & 1) ? sKB1 : sKB0;
            const float* src = vbase + (c + 1) * 128 * 32;
#pragma unroll
            for (int i = 0; i < 4; i++) {
                int idx = t + i * 256;
                int k = idx >> 3, seg = idx & 7;
                cp_async16(dst + k * 144 + seg * 16, src + k * 32 + seg * 4);
            }
            cp_commit();
            cp_wait<1>();
        } else {
            cp_wait<0>();
        }
        __syncthreads();

        const float* buf = (c & 1) ? KB1 : KB0;
#pragma unroll
        for (int ks = 0; ks < 2; ks++) {
            int kb = w * 16 + ks * 8;
            uint32 a[2][4];
#pragma unroll
            for (int mt = 0; mt < 2; mt++) {
                const float* ab = S + (mt * 16 + lq) * 516 + c * 128 + kb + lc;
                a[mt][0] = cvt_tf32(ab[0]);
                a[mt][1] = cvt_tf32(ab[8 * 516]);
                a[mt][2] = cvt_tf32(ab[4]);
                a[mt][3] = cvt_tf32(ab[8 * 516 + 4]);
            }
#pragma unroll
            for (int nt = 0; nt < 4; nt++) {
                int dn = nt * 8 + lq;
                uint32 b0 = __float_as_uint(buf[(kb + lc) * 36 + dn]);
                uint32 b1 = __float_as_uint(buf[(kb + lc + 4) * 36 + dn]);
                mma_tf32(cv[0][nt], a[0], b0, b1);
                mma_tf32(cv[1][nt], a[1], b0, b1);
            }
        }
    }
    __syncthreads();

    // two-stage cross-warp reduction (red in KB0 region: 4 x 1088 floats)
    float* red = KB0;
    if (w >= 4) {
        float* rg = red + (w - 4) * 1088;
#pragma unroll
        for (int mt = 0; mt < 2; mt++)
#pragma unroll
            for (int nt = 0; nt < 4; nt++) {
                int r0 = mt * 16 + lq, dc = nt * 8 + 2 * lc;
                *(float2*)(rg + r0 * 34 + dc) = make_float2(cv[mt][nt][0], cv[mt][nt][1]);
                *(float2*)(rg + (r0 + 8) * 34 + dc) = make_float2(cv[mt][nt][2], cv[mt][nt][3]);
            }
    }
    __syncthreads();
    if (w < 4) {
        float* rg = red + w * 1088;
#pragma unroll
        for (int mt = 0; mt < 2; mt++)
#pragma unroll
            for (int nt = 0; nt < 4; nt++) {
                int r0 = mt * 16 + lq, dc = nt * 8 + 2 * lc;
                float2 p0 = *(const float2*)(rg + r0 * 34 + dc);
                float2 p1 = *(const float2*)(rg + (r0 + 8) * 34 + dc);
                *(float2*)(rg + r0 * 34 + dc) =
                    make_float2(cv[mt][nt][0] + p0.x, cv[mt][nt][1] + p0.y);
                *(float2*)(rg + (r0 + 8) * 34 + dc) =
                    make_float2(cv[mt][nt][2] + p1.x, cv[mt][nt][3] + p1.y);
            }
    }
    __syncthreads();
    {
        int q = t >> 3, d4 = (t & 7) * 4;
        float iv = invp[q];
        float o[4];
#pragma unroll
        for (int j = 0; j < 4; j++) {
            int off = q * 34 + d4 + j;
            o[j] = red[off] + red[1088 + off] + red[2176 + off] + red[3264 + off];
        }
        float4 ov = make_float4(o[0] * iv, o[1] * iv, o[2] * iv, o[3] * iv);
        *(float4*)(g_ctx + ((size_t)(b * LL) + q0 + q) * DD + h * DH + d4) = ov;
    }
}

// ---------------- kernel 3: output GEMM ctx @ Wo + bo (tf32, 3-MMA split) ----------------
__global__ __launch_bounds__(256) void out_gemm_kernel(
        const float* __restrict__ Wo,
        const float* __restrict__ bo,
        float* __restrict__ out) {
    __shared__ float As[64 * 68];
    __shared__ float Bs[64 * 68];

    const int t = threadIdx.x;
    const int w = t >> 5, lane = t & 31;
    const int lq = lane >> 2, lc = lane & 3;
    const int wm = w >> 2, wn = w & 3;
    const int rowBase = blockIdx.y * 64;
    const int colBase = blockIdx.x * 64;

    float cc[2][2][4];
#pragma unroll
    for (int mt = 0; mt < 2; mt++)
#pragma unroll
        for (int nt = 0; nt < 2; nt++)
#pragma unroll
            for (int e = 0; e < 4; e++) cc[mt][nt][e] = 0.0f;

    for (int k0 = 0; k0 < DD; k0 += 64) {
        for (int i = t; i < 1024; i += 256) {
            int m = i >> 4, k4 = (i & 15) * 4;
            *(float4*)(As + m * 68 + k4) = *(const float4*)(g_ctx + (rowBase + m) * DD + k0 + k4);
        }
        for (int i = t; i < 1024; i += 256) {
            int k = i >> 4, n4 = (i & 15) * 4;
            *(float4*)(Bs + k * 68 + n4) = *(const float4*)(Wo + (k0 + k) * DD + colBase + n4);
        }
        __syncthreads();
#pragma unroll
        for (int ks = 0; ks < 8; ks++) {
            uint32 ah[2][4], al[2][4];
#pragma unroll
            for (int mt = 0; mt < 2; mt++) {
                const float* ab = As + (wm * 32 + mt * 16 + lq) * 68 + ks * 8 + lc;
                float x0 = ab[0], x1 = ab[8 * 68], x2 = ab[4], x3 = ab[8 * 68 + 4];
                ah[mt][0] = cvt_tf32(x0); al[mt][0] = cvt_tf32(x0 - __uint_as_float(ah[mt][0]));
                ah[mt][1] = cvt_tf32(x1); al[mt][1] = cvt_tf32(x1 - __uint_as_float(ah[mt][1]));
                ah[mt][2] = cvt_tf32(x2); al[mt][2] = cvt_tf32(x2 - __uint_as_float(ah[mt][2]));
                ah[mt][3] = cvt_tf32(x3); al[mt][3] = cvt_tf32(x3 - __uint_as_float(ah[mt][3]));
            }
#pragma unroll
            for (int nt = 0; nt < 2; nt++) {
                const float* bb = Bs + (ks * 8 + lc) * 68 + wn * 16 + nt * 8 + lq;
                float w0 = bb[0], w1 = bb[4 * 68];
                uint32 bh0 = cvt_tf32(w0);
                uint32 bl0 = cvt_tf32(w0 - __uint_as_float(bh0));
                uint32 bh1 = cvt_tf32(w1);
                uint32 bl1 = cvt_tf32(w1 - __uint_as_float(bh1));
                mma_tf32(cc[0][nt], ah[0], bh0, bh1);
                mma_tf32(cc[0][nt], al[0], bh0, bh1);
                mma_tf32(cc[0][nt], ah[0], bl0, bl1);
                mma_tf32(cc[1][nt], ah[1], bh0, bh1);
                mma_tf32(cc[1][nt], al[1], bh0, bh1);
                mma_tf32(cc[1][nt], ah[1], bl0, bl1);
            }
        }
        __syncthreads();
    }

#pragma unroll
    for (int mt = 0; mt < 2; mt++) {
#pragma unroll
        for (int nt = 0; nt < 2; nt++) {
            int col0 = colBase + wn * 16 + nt * 8 + 2 * lc;
            float bx = bo[col0], by = bo[col0 + 1];
            int r0 = rowBase + wm * 32 + mt * 16 + lq;
            *(float2*)(out + r0 * DD + col0) =
                make_float2(cc[mt][nt][0] + bx, cc[mt][nt][1] + by);
            *(float2*)(out + (r0 + 8) * DD + col0) =
                make_float2(cc[mt][nt][2] + bx, cc[mt][nt][3] + by);
        }
    }
}

// ---------------- launch ----------------
extern "C" void kernel_launch(void* const* d_in, const int* in_sizes, int n_in,
                              void* d_out, int out_size) {
    const float* X         = (const float*)d_in[0];
    const void*  mask      = d_in[1];
    const int*   distances = (const int*)d_in[2];
    const float* Wq        = (const float*)d_in[3];
    const float* bq        = (const float*)d_in[4];
    const float* Wk        = (const float*)d_in[5];
    const float* bk        = (const float*)d_in[6];
    const float* Wv        = (const float*)d_in[7];
    const float* bv        = (const float*)d_in[8];
    const float* Wo        = (const float*)d_in[9];
    const float* bo        = (const float*)d_in[10];
    const float* rel_table = (const float*)d_in[11];
    const float* uvec      = (const float*)d_in[12];
    const float* vvec      = (const float*)d_in[13];

    float* out  = (float*)d_out;                       // (B,L,D)
    float* attn = (float*)d_out + BB * LL * DD;        // (B,H,L,L)

    const int attn_smem = 27328 * 4;
    static int smem_set = 0;
    if (!smem_set) {
        cudaFuncSetAttribute(attn_kernel,
                             cudaFuncAttributeMaxDynamicSharedMemorySize,
                             attn_smem);
        smem_set = 1;
    }

    detect_mask_kernel<<<1, 256>>>((const unsigned int*)mask);
    prep_idx_kernel<<<1024, 256>>>(mask, distances);
    qkv_gemm_kernel<<<dim3(4, 32, 3), 256>>>(X, Wq, bq, Wk, bk, Wv, bv);
    attn_kernel<<<dim3(16, 32), 256, attn_smem>>>(uvec, vvec, rel_table, attn);
    out_gemm_kernel<<<dim3(4, 32), 256>>>(Wo, bo, out);
}

// round 9
// speedup vs baseline: 1.3461x; 1.0027x over previous
#include <cuda_runtime.h>
#include <cuda_bf16.h>

// Problem constants
#define BB 4
#define LL 512
#define DD 256
#define HH 8
#define DH 32
#define QK_SCALE 0.17677669529663687f  // 1/sqrt(32)

typedef unsigned long long ull;
typedef unsigned int uint32;

// ---------------- tf32 mma helpers ----------------
__device__ __forceinline__ void mma_tf32(float* c, const uint32* a, uint32 b0, uint32 b1) {
    asm volatile(
        "mma.sync.aligned.m16n8k8.row.col.f32.tf32.tf32.f32 "
        "{%0,%1,%2,%3}, {%4,%5,%6,%7}, {%8,%9}, {%0,%1,%2,%3};"
        : "+f"(c[0]), "+f"(c[1]), "+f"(c[2]), "+f"(c[3])
        : "r"(a[0]), "r"(a[1]), "r"(a[2]), "r"(a[3]), "r"(b0), "r"(b1));
}
__device__ __forceinline__ uint32 cvt_tf32(float f) {
    uint32 u; asm("cvt.rna.tf32.f32 %0, %1;" : "=r"(u) : "f"(f)); return u;
}

// ---------------- cp.async helpers ----------------
__device__ __forceinline__ void cp_async16(uint32 s, const void* g) {
    asm volatile("cp.async.cg.shared.global [%0], [%1], 16;" :: "r"(s), "l"(g));
}
__device__ __forceinline__ void cp_commit() {
    asm volatile("cp.async.commit_group;");
}
template <int N>
__device__ __forceinline__ void cp_wait() {
    asm volatile("cp.async.wait_group %0;" :: "n"(N));
}

// ---------------- device scratch ----------------
__device__ float g_q[BB * HH * LL * DH];   // scaled q, (B,H,L,DH)
__device__ float g_k[BB * HH * LL * DH];
__device__ float g_v[BB * HH * LL * DH];
__device__ float g_ctx[BB * LL * DD];      // ctx in (B,L,D) layout
__device__ unsigned char g_idx[BB * LL * LL]; // fused mask+distance bucket index
__device__ int   g_mask_kind;              // 0=int32, 1=float32, 2=bytes

// ---------------- mask dtype detector ----------------
__global__ void detect_mask_kernel(const unsigned int* mw) {
    __shared__ int flags[2];
    if (threadIdx.x < 2) flags[threadIdx.x] = 0;
    __syncthreads();
    int f1 = 0, f2 = 0;
    for (int i = threadIdx.x; i < 4096; i += blockDim.x) {
        unsigned int w = mw[i];
        if (w == 0u || w == 1u) continue;
        if (w == 0x3F800000u) { f1 = 1; continue; }
        f2 = 1;
    }
    if (f1) atomicOr(&flags[0], 1);
    if (f2) atomicOr(&flags[1], 1);
    __syncthreads();
    if (threadIdx.x == 0)
        g_mask_kind = flags[1] ? 2 : (flags[0] ? 1 : 0);
}

// ---------------- prep: idx = mask ? 12 : dist (bytes) ----------------
__global__ void prep_idx_kernel(const void* __restrict__ mask,
                                const int* __restrict__ dist) {
    const int kind = g_mask_kind;
    const int i = blockIdx.x * 256 + threadIdx.x;
    int4 d4 = ((const int4*)dist)[i];
    int m0, m1, m2, m3;
    if (kind == 2) {
        uchar4 m = ((const uchar4*)mask)[i];
        m0 = m.x; m1 = m.y; m2 = m.z; m3 = m.w;
    } else if (kind == 1) {
        float4 m = ((const float4*)mask)[i];
        m0 = (m.x != 0.0f); m1 = (m.y != 0.0f); m2 = (m.z != 0.0f); m3 = (m.w != 0.0f);
    } else {
        int4 m = ((const int4*)mask)[i];
        m0 = m.x; m1 = m.y; m2 = m.z; m3 = m.w;
    }
    uchar4 o;
    o.x = m0 ? 12 : (unsigned char)d4.x;
    o.y = m1 ? 12 : (unsigned char)d4.y;
    o.z = m2 ? 12 : (unsigned char)d4.z;
    o.w = m3 ? 12 : (unsigned char)d4.w;
    ((uchar4*)g_idx)[i] = o;
}

// ---------------- kernel 1: fused QKV GEMM (tf32 3-MMA, hoisted split) ----------------
// dynamic smem: Ah/Al/Bh/Bl each 64*68 floats
__global__ __launch_bounds__(256) void qkv_gemm_kernel(
        const float* __restrict__ X,
        const float* __restrict__ Wq, const float* __restrict__ bq,
        const float* __restrict__ Wk, const float* __restrict__ bk,
        const float* __restrict__ Wv, const float* __restrict__ bv) {
    const int z = blockIdx.z;
    const float* W    = (z == 0) ? Wq : (z == 1 ? Wk : Wv);
    const float* bias = (z == 0) ? bq : (z == 1 ? bk : bv);
    float* out        = (z == 0) ? g_q : (z == 1 ? g_k : g_v);
    const float scale = (z == 0) ? QK_SCALE : 1.0f;

    extern __shared__ float dsm[];
    float* Ah = dsm;                 // [m][k] 64*68
    float* Al = dsm + 4352;
    float* Bh = dsm + 8704;          // [k][n] 64*68
    float* Bl = dsm + 13056;

    const int t = threadIdx.x;
    const int w = t >> 5, lane = t & 31;
    const int lq = lane >> 2, lc = lane & 3;
    const int wm = w >> 2, wn = w & 3;
    const int rowBase = blockIdx.y * 64;
    const int colBase = blockIdx.x * 64;

    float cc[2][2][4];
#pragma unroll
    for (int mt = 0; mt < 2; mt++)
#pragma unroll
        for (int nt = 0; nt < 2; nt++)
#pragma unroll
            for (int e = 0; e < 4; e++) cc[mt][nt][e] = 0.0f;

    for (int k0 = 0; k0 < DD; k0 += 64) {
        for (int i = t; i < 1024; i += 256) {
            int m = i >> 4, k4 = (i & 15) * 4;
            float4 x = *(const float4*)(X + (rowBase + m) * DD + k0 + k4);
            float h0 = __uint_as_float(cvt_tf32(x.x));
            float h1 = __uint_as_float(cvt_tf32(x.y));
            float h2 = __uint_as_float(cvt_tf32(x.z));
            float h3 = __uint_as_float(cvt_tf32(x.w));
            *(float4*)(Ah + m * 68 + k4) = make_float4(h0, h1, h2, h3);
            *(float4*)(Al + m * 68 + k4) = make_float4(
                __uint_as_float(cvt_tf32(x.x - h0)), __uint_as_float(cvt_tf32(x.y - h1)),
                __uint_as_float(cvt_tf32(x.z - h2)), __uint_as_float(cvt_tf32(x.w - h3)));
        }
        for (int i = t; i < 1024; i += 256) {
            int k = i >> 4, n4 = (i & 15) * 4;
            float4 x = *(const float4*)(W + (k0 + k) * DD + colBase + n4);
            float h0 = __uint_as_float(cvt_tf32(x.x));
            float h1 = __uint_as_float(cvt_tf32(x.y));
            float h2 = __uint_as_float(cvt_tf32(x.z));
            float h3 = __uint_as_float(cvt_tf32(x.w));
            *(float4*)(Bh + k * 68 + n4) = make_float4(h0, h1, h2, h3);
            *(float4*)(Bl + k * 68 + n4) = make_float4(
                __uint_as_float(cvt_tf32(x.x - h0)), __uint_as_float(cvt_tf32(x.y - h1)),
                __uint_as_float(cvt_tf32(x.z - h2)), __uint_as_float(cvt_tf32(x.w - h3)));
        }
        __syncthreads();
#pragma unroll
        for (int ks = 0; ks < 8; ks++) {
            uint32 ah[2][4], al[2][4];
#pragma unroll
            for (int mt = 0; mt < 2; mt++) {
                int off = (wm * 32 + mt * 16 + lq) * 68 + ks * 8 + lc;
                ah[mt][0] = __float_as_uint(Ah[off]);
                ah[mt][1] = __float_as_uint(Ah[off + 8 * 68]);
                ah[mt][2] = __float_as_uint(Ah[off + 4]);
                ah[mt][3] = __float_as_uint(Ah[off + 8 * 68 + 4]);
                al[mt][0] = __float_as_uint(Al[off]);
                al[mt][1] = __float_as_uint(Al[off + 8 * 68]);
                al[mt][2] = __float_as_uint(Al[off + 4]);
                al[mt][3] = __float_as_uint(Al[off + 8 * 68 + 4]);
            }
#pragma unroll
            for (int nt = 0; nt < 2; nt++) {
                int off = (ks * 8 + lc) * 68 + wn * 16 + nt * 8 + lq;
                uint32 bh0 = __float_as_uint(Bh[off]);
                uint32 bh1 = __float_as_uint(Bh[off + 4 * 68]);
                uint32 bl0 = __float_as_uint(Bl[off]);
                uint32 bl1 = __float_as_uint(Bl[off + 4 * 68]);
                mma_tf32(cc[0][nt], ah[0], bh0, bh1);
                mma_tf32(cc[0][nt], al[0], bh0, bh1);
                mma_tf32(cc[0][nt], ah[0], bl0, bl1);
                mma_tf32(cc[1][nt], ah[1], bh0, bh1);
                mma_tf32(cc[1][nt], al[1], bh0, bh1);
                mma_tf32(cc[1][nt], ah[1], bl0, bl1);
            }
        }
        __syncthreads();
    }

#pragma unroll
    for (int mt = 0; mt < 2; mt++) {
#pragma unroll
        for (int nt = 0; nt < 2; nt++) {
            int col0 = colBase + wn * 16 + nt * 8 + 2 * lc;
            int h = col0 >> 5, d = col0 & 31;
            float bx = bias[col0], by = bias[col0 + 1];
            int r0 = rowBase + wm * 32 + mt * 16 + lq;
            {
                int b = r0 >> 9, l = r0 & 511;
                float2 o = make_float2((cc[mt][nt][0] + bx) * scale,
                                       (cc[mt][nt][1] + by) * scale);
                *(float2*)(out + (((b * HH + h) * LL) + l) * DH + d) = o;
            }
            {
                int r1 = r0 + 8;
                int b = r1 >> 9, l = r1 & 511;
                float2 o = make_float2((cc[mt][nt][2] + bx) * scale,
                                       (cc[mt][nt][3] + by) * scale);
                *(float2*)(out + (((b * HH + h) * LL) + l) * DH + d) = o;
            }
        }
    }
}

// ---------------- kernel 2: fused attention, 16-q tiles, 3 CTAs/SM ----------------
// smem floats: S 16*516=8256 | KB0 4608 | KB1 4608 | qu 528 | Ps 256 | invp 16 = 18272
__global__ __launch_bounds__(256, 3) void attn_kernel(
        const float* __restrict__ uvec,
        const float* __restrict__ vvec,
        const float* __restrict__ rel_table,
        float* __restrict__ attn) {
    extern __shared__ float sm[];
    float* S    = sm;                    // [16][516]
    float* KB0  = sm + 8256;             // [128][36]
    float* KB1  = sm + 12864;            // [128][36]
    float* qu   = sm + 17472;            // [16][33]
    float* Ps   = qu + 528;              // [16][16]
    float* invp = Ps + 256;              // [16]

    const int bh = blockIdx.y;
    const int b = bh >> 3, h = bh & 7;
    const int q0 = blockIdx.x * 16;
    const int t = threadIdx.x;
    const int w = t >> 5;
    const int lane = t & 31;
    const int lq = lane >> 2;
    const int lc = lane & 3;

    const float* kbase = g_k + (size_t)bh * LL * DH;
    const float* vbase = g_v + (size_t)bh * LL * DH;
    const uint32 sKB0 = (uint32)__cvta_generic_to_shared(KB0);
    const uint32 sKB1 = (uint32)__cvta_generic_to_shared(KB1);

    // prefetch K chunk 0 into KB0
    {
#pragma unroll
        for (int i = 0; i < 4; i++) {
            int idx = t + i * 256;
            int k = idx >> 3, seg = idx & 7;
            cp_async16(sKB0 + k * 144 + seg * 16, kbase + k * 32 + seg * 4);
        }
        cp_commit();
    }

    // -------- phase 0: qu = q+v, table slice (in KB1), P --------
    if (t < 128) {
        int q = t >> 3, d4 = (t & 7) * 4;
        float4 qv = *(const float4*)(g_q + ((size_t)bh * LL + q0 + q) * DH + d4);
        float4 vv = *(const float4*)(vvec + h * DH + d4);
        qu[q * 33 + d4 + 0] = qv.x + vv.x;
        qu[q * 33 + d4 + 1] = qv.y + vv.y;
        qu[q * 33 + d4 + 2] = qv.z + vv.z;
        qu[q * 33 + d4 + 3] = qv.w + vv.w;
    }
    float* tbl = KB1;   // [12][33]
    for (int i = t; i < 384; i += 256) {
        int bu = i >> 5, d = i & 31;
        tbl[bu * 33 + d] = rel_table[bu * DD + h * DH + d];
    }
    __syncthreads();
    if (t < 192) {
        int q = t / 12, bu = t - q * 12;
        const float* qp = qu + q * 33;
        const float* tp = tbl + bu * 33;
        float s = 0.0f;
#pragma unroll
        for (int d = 0; d < 32; d++) s = fmaf(qp[d], tp[d], s);
        Ps[q * 16 + bu] = s;
    }
    if (t < 16) Ps[t * 16 + 12] = -1e18f;
    __syncthreads();
    // qu: (q+v) -> (q+u)
    if (t < 128) {
        int q = t >> 3, d4 = (t & 7) * 4;
        float4 uu = *(const float4*)(uvec + h * DH + d4);
        float4 vv = *(const float4*)(vvec + h * DH + d4);
        qu[q * 33 + d4 + 0] += uu.x - vv.x;
        qu[q * 33 + d4 + 1] += uu.y - vv.y;
        qu[q * 33 + d4 + 2] += uu.z - vv.z;
        qu[q * 33 + d4 + 3] += uu.w - vv.w;
    }

    // -------- phase 1: scores via tf32 mma, 4 chunks of 128 k, double-buffered --------
#pragma unroll 1
    for (int c = 0; c < 4; c++) {
        __syncthreads();
        if (c < 3) {
            uint32 dst = ((c + 1) & 1) ? sKB1 : sKB0;
            const float* src = kbase + (c + 1) * 128 * 32;
#pragma unroll
            for (int i = 0; i < 4; i++) {
                int idx = t + i * 256;
                int k = idx >> 3, seg = idx & 7;
                cp_async16(dst + k * 144 + seg * 16, src + k * 32 + seg * 4);
            }
            cp_commit();
        } else {
            // prefetch V chunk 0 into KB0
#pragma unroll
            for (int i = 0; i < 4; i++) {
                int idx = t + i * 256;
                int k = idx >> 3, seg = idx & 7;
                cp_async16(sKB0 + k * 144 + seg * 16, vbase + k * 32 + seg * 4);
            }
            cp_commit();
        }
        cp_wait<1>();
        __syncthreads();

        const float* buf = (c & 1) ? KB1 : KB0;
        float cc[2][4];
#pragma unroll
        for (int nt = 0; nt < 2; nt++)
#pragma unroll
            for (int e = 0; e < 4; e++) cc[nt][e] = 0.0f;

#pragma unroll
        for (int ks = 0; ks < 4; ks++) {
            uint32 a[4];
            {
                int off = lq * 33 + ks * 8 + lc;
                a[0] = __float_as_uint(qu[off]);
                a[1] = __float_as_uint(qu[off + 8 * 33]);
                a[2] = __float_as_uint(qu[off + 4]);
                a[3] = __float_as_uint(qu[off + 8 * 33 + 4]);
            }
#pragma unroll
            for (int nt = 0; nt < 2; nt++) {
                int kn = w * 16 + nt * 8 + lq;
                uint32 b0 = __float_as_uint(buf[kn * 36 + ks * 8 + lc]);
                uint32 b1 = __float_as_uint(buf[kn * 36 + ks * 8 + lc + 4]);
                mma_tf32(cc[nt], a, b0, b1);
            }
        }

        int kc = c * 128;
#pragma unroll
        for (int nt = 0; nt < 2; nt++) {
            int kk = kc + w * 16 + nt * 8 + 2 * lc;
            unsigned int u0 = *(const unsigned short*)
                (g_idx + ((size_t)(b * LL + q0 + lq)) * LL + kk);
            unsigned int u1 = *(const unsigned short*)
                (g_idx + ((size_t)(b * LL + q0 + lq + 8)) * LL + kk);
            const float* P0 = Ps + lq * 16;
            const float* P1 = Ps + (lq + 8) * 16;
            float2 o0, o1;
            o0.x = cc[nt][0] + P0[u0 & 255];
            o0.y = cc[nt][1] + P0[(u0 >> 8) & 255];
            o1.x = cc[nt][2] + P1[u1 & 255];
            o1.y = cc[nt][3] + P1[(u1 >> 8) & 255];
            *(float2*)(S + lq * 516 + kk) = o0;
            *(float2*)(S + (lq + 8) * 516 + kk) = o1;
        }
    }
    __syncthreads();

    // -------- phase 2: softmax rows (V chunk 0 streaming in behind) --------
    {
#pragma unroll
        for (int rr = 0; rr < 2; rr++) {
            int r = w * 2 + rr;
            float* Sr = S + r * 516;
            float m = -3.4e38f;
            for (int cix = lane; cix < LL; cix += 32) m = fmaxf(m, Sr[cix]);
#pragma unroll
            for (int o = 16; o; o >>= 1) m = fmaxf(m, __shfl_xor_sync(0xffffffffu, m, o));
            float s = 0.0f;
            for (int cix = lane; cix < LL; cix += 32) {
                float e = __expf(Sr[cix] - m);
                Sr[cix] = e;
                s += e;
            }
#pragma unroll
            for (int o = 16; o; o >>= 1) s += __shfl_xor_sync(0xffffffffu, s, o);
            if (lane == 0) invp[r] = 1.0f / s;
        }
    }
    __syncthreads();

    // write normalized attn
    float* arow = attn + ((size_t)(bh * LL + q0)) * LL;
    for (int i = t; i < 16 * 128; i += 256) {
        int r = i >> 7, c4 = (i & 127) << 2;
        float iv = invp[r];
        float4 e = *(const float4*)(S + r * 516 + c4);
        float4 o = make_float4(e.x * iv, e.y * iv, e.z * iv, e.w * iv);
        *(float4*)(arow + r * LL + c4) = o;
    }

    // -------- phase 3: ctx = S @ V via tf32 mma, double-buffered V --------
    float cv[4][4];
#pragma unroll
    for (int nt = 0; nt < 4; nt++)
#pragma unroll
        for (int e = 0; e < 4; e++) cv[nt][e] = 0.0f;

#pragma unroll 1
    for (int c = 0; c < 4; c++) {
        __syncthreads();
        if (c < 3) {
            uint32 dst = ((c + 1) & 1) ? sKB1 : sKB0;
            const float* src = vbase + (c + 1) * 128 * 32;
#pragma unroll
            for (int i = 0; i < 4; i++) {
                int idx = t + i * 256;
                int k = idx >> 3, seg = idx & 7;
                cp_async16(dst + k * 144 + seg * 16, src + k * 32 + seg * 4);
            }
            cp_commit();
            cp_wait<1>();
        } else {
            cp_wait<0>();
        }
        __syncthreads();

        const float* buf = (c & 1) ? KB1 : KB0;
#pragma unroll
        for (int ks = 0; ks < 2; ks++) {
            int kb = w * 16 + ks * 8;
            uint32 a[4];
            {
                const float* ab = S + lq * 516 + c * 128 + kb + lc;
                a[0] = cvt_tf32(ab[0]);
                a[1] = cvt_tf32(ab[8 * 516]);
                a[2] = cvt_tf32(ab[4]);
                a[3] = cvt_tf32(ab[8 * 516 + 4]);
            }
#pragma unroll
            for (int nt = 0; nt < 4; nt++) {
                int dn = nt * 8 + lq;
                uint32 b0 = __float_as_uint(buf[(kb + lc) * 36 + dn]);
                uint32 b1 = __float_as_uint(buf[(kb + lc + 4) * 36 + dn]);
                mma_tf32(cv[nt], a, b0, b1);
            }
        }
    }
    __syncthreads();

    // two-stage cross-warp reduction: 8 partials [16][34] in KB0 (8*544=4352)
    float* red = KB0;
    if (w >= 4) {
        float* rg = red + (w - 4) * 544;
#pragma unroll
        for (int nt = 0; nt < 4; nt++) {
            int dc = nt * 8 + 2 * lc;
            *(float2*)(rg + lq * 34 + dc) = make_float2(cv[nt][0], cv[nt][1]);
            *(float2*)(rg + (lq + 8) * 34 + dc) = make_float2(cv[nt][2], cv[nt][3]);
        }
    }
    __syncthreads();
    if (w < 4) {
        float* rg = red + w * 544;
#pragma unroll
        for (int nt = 0; nt < 4; nt++) {
            int dc = nt * 8 + 2 * lc;
            float2 p0 = *(const float2*)(rg + lq * 34 + dc);
            float2 p1 = *(const float2*)(rg + (lq + 8) * 34 + dc);
            *(float2*)(rg + lq * 34 + dc) =
                make_float2(cv[nt][0] + p0.x, cv[nt][1] + p0.y);
            *(float2*)(rg + (lq + 8) * 34 + dc) =
                make_float2(cv[nt][2] + p1.x, cv[nt][3] + p1.y);
        }
    }
    __syncthreads();
    if (t < 128) {
        int q = t >> 3, d4 = (t & 7) * 4;
        float iv = invp[q];
        float o[4];
#pragma unroll
        for (int j = 0; j < 4; j++) {
            int off = q * 34 + d4 + j;
            o[j] = red[off] + red[544 + off] + red[1088 + off] + red[1632 + off];
        }
        float4 ov = make_float4(o[0] * iv, o[1] * iv, o[2] * iv, o[3] * iv);
        *(float4*)(g_ctx + ((size_t)(b * LL) + q0 + q) * DD + h * DH + d4) = ov;
    }
}

// ---------------- kernel 3: output GEMM (tf32 3-MMA, hoisted split) ----------------
__global__ __launch_bounds__(256) void out_gemm_kernel(
        const float* __restrict__ Wo,
        const float* __restrict__ bo,
        float* __restrict__ out) {
    extern __shared__ float dsm[];
    float* Ah = dsm;
    float* Al = dsm + 4352;
    float* Bh = dsm + 8704;
    float* Bl = dsm + 13056;

    const int t = threadIdx.x;
    const int w = t >> 5, lane = t & 31;
    const int lq = lane >> 2, lc = lane & 3;
    const int wm = w >> 2, wn = w & 3;
    const int rowBase = blockIdx.y * 64;
    const int colBase = blockIdx.x * 64;

    float cc[2][2][4];
#pragma unroll
    for (int mt = 0; mt < 2; mt++)
#pragma unroll
        for (int nt = 0; nt < 2; nt++)
#pragma unroll
            for (int e = 0; e < 4; e++) cc[mt][nt][e] = 0.0f;

    for (int k0 = 0; k0 < DD; k0 += 64) {
        for (int i = t; i < 1024; i += 256) {
            int m = i >> 4, k4 = (i & 15) * 4;
            float4 x = *(const float4*)(g_ctx + (rowBase + m) * DD + k0 + k4);
            float h0 = __uint_as_float(cvt_tf32(x.x));
            float h1 = __uint_as_float(cvt_tf32(x.y));
            float h2 = __uint_as_float(cvt_tf32(x.z));
            float h3 = __uint_as_float(cvt_tf32(x.w));
            *(float4*)(Ah + m * 68 + k4) = make_float4(h0, h1, h2, h3);
            *(float4*)(Al + m * 68 + k4) = make_float4(
                __uint_as_float(cvt_tf32(x.x - h0)), __uint_as_float(cvt_tf32(x.y - h1)),
                __uint_as_float(cvt_tf32(x.z - h2)), __uint_as_float(cvt_tf32(x.w - h3)));
        }
        for (int i = t; i < 1024; i += 256) {
            int k = i >> 4, n4 = (i & 15) * 4;
            float4 x = *(const float4*)(Wo + (k0 + k) * DD + colBase + n4);
            float h0 = __uint_as_float(cvt_tf32(x.x));
            float h1 = __uint_as_float(cvt_tf32(x.y));
            float h2 = __uint_as_float(cvt_tf32(x.z));
            float h3 = __uint_as_float(cvt_tf32(x.w));
            *(float4*)(Bh + k * 68 + n4) = make_float4(h0, h1, h2, h3);
            *(float4*)(Bl + k * 68 + n4) = make_float4(
                __uint_as_float(cvt_tf32(x.x - h0)), __uint_as_float(cvt_tf32(x.y - h1)),
                __uint_as_float(cvt_tf32(x.z - h2)), __uint_as_float(cvt_tf32(x.w - h3)));
        }
        __syncthreads();
#pragma unroll
        for (int ks = 0; ks < 8; ks++) {
            uint32 ah[2][4], al[2][4];
#pragma unroll
            for (int mt = 0; mt < 2; mt++) {
                int off = (wm * 32 + mt * 16 + lq) * 68 + ks * 8 + lc;
                ah[mt][0] = __float_as_uint(Ah[off]);
                ah[mt][1] = __float_as_uint(Ah[off + 8 * 68]);
                ah[mt][2] = __float_as_uint(Ah[off + 4]);
                ah[mt][3] = __float_as_uint(Ah[off + 8 * 68 + 4]);
                al[mt][0] = __float_as_uint(Al[off]);
                al[mt][1] = __float_as_uint(Al[off + 8 * 68]);
                al[mt][2] = __float_as_uint(Al[off + 4]);
                al[mt][3] = __float_as_uint(Al[off + 8 * 68 + 4]);
            }
#pragma unroll
            for (int nt = 0; nt < 2; nt++) {
                int off = (ks * 8 + lc) * 68 + wn * 16 + nt * 8 + lq;
                uint32 bh0 = __float_as_uint(Bh[off]);
                uint32 bh1 = __float_as_uint(Bh[off + 4 * 68]);
                uint32 bl0 = __float_as_uint(Bl[off]);
                uint32 bl1 = __float_as_uint(Bl[off + 4 * 68]);
                mma_tf32(cc[0][nt], ah[0], bh0, bh1);
                mma_tf32(cc[0][nt], al[0], bh0, bh1);
                mma_tf32(cc[0][nt], ah[0], bl0, bl1);
                mma_tf32(cc[1][nt], ah[1], bh0, bh1);
                mma_tf32(cc[1][nt], al[1], bh0, bh1);
                mma_tf32(cc[1][nt], ah[1], bl0, bl1);
            }
        }
        __syncthreads();
    }

#pragma unroll
    for (int mt = 0; mt < 2; mt++) {
#pragma unroll
        for (int nt = 0; nt < 2; nt++) {
            int col0 = colBase + wn * 16 + nt * 8 + 2 * lc;
            float bx = bo[col0], by = bo[col0 + 1];
            int r0 = rowBase + wm * 32 + mt * 16 + lq;
            *(float2*)(out + r0 * DD + col0) =
                make_float2(cc[mt][nt][0] + bx, cc[mt][nt][1] + by);
            *(float2*)(out + (r0 + 8) * DD + col0) =
                make_float2(cc[mt][nt][2] + bx, cc[mt][nt][3] + by);
        }
    }
}

// ---------------- launch ----------------
extern "C" void kernel_launch(void* const* d_in, const int* in_sizes, int n_in,
                              void* d_out, int out_size) {
    const float* X         = (const float*)d_in[0];
    const void*  mask      = d_in[1];
    const int*   distances = (const int*)d_in[2];
    const float* Wq        = (const float*)d_in[3];
    const float* bq        = (const float*)d_in[4];
    const float* Wk        = (const float*)d_in[5];
    const float* bk        = (const float*)d_in[6];
    const float* Wv        = (const float*)d_in[7];
    const float* bv        = (const float*)d_in[8];
    const float* Wo        = (const float*)d_in[9];
    const float* bo        = (const float*)d_in[10];
    const float* rel_table = (const float*)d_in[11];
    const float* uvec      = (const float*)d_in[12];
    const float* vvec      = (const float*)d_in[13];

    float* out  = (float*)d_out;                       // (B,L,D)
    float* attn = (float*)d_out + BB * LL * DD;        // (B,H,L,L)

    const int attn_smem = 18272 * 4;      // 73088 B
    const int gemm_smem = 17408 * 4;      // 69632 B
    static int smem_set = 0;
    if (!smem_set) {
        cudaFuncSetAttribute(attn_kernel,
                             cudaFuncAttributeMaxDynamicSharedMemorySize, attn_smem);
        cudaFuncSetAttribute(qkv_gemm_kernel,
                             cudaFuncAttributeMaxDynamicSharedMemorySize, gemm_smem);
        cudaFuncSetAttribute(out_gemm_kernel,
                             cudaFuncAttributeMaxDynamicSharedMemorySize, gemm_smem);
        smem_set = 1;
    }

    detect_mask_kernel<<<1, 256>>>((const unsigned int*)mask);
    prep_idx_kernel<<<1024, 256>>>(mask, distances);
    qkv_gemm_kernel<<<dim3(4, 32, 3), 256, gemm_smem>>>(X, Wq, bq, Wk, bk, Wv, bv);
    attn_kernel<<<dim3(32, 32), 256, attn_smem>>>(uvec, vvec, rel_table, attn);
    out_gemm_kernel<<<dim3(4, 32), 256, gemm_smem>>>(Wo, bo, out);
}